// round 2
// baseline (speedup 1.0000x reference)
#include <cuda_runtime.h>
#include <math.h>
#include <math_constants.h>

// Problem constants
#define BATCH  32
#define SEQ    4096
#define DDIM   1024
#define NTOK   (BATCH*SEQ)     // 131072
#define NHEAD  16
#define HD     64
#define RLAT   64
#define SCALE  0.125f          // R^-0.5

// ---------------------------------------------------------------------------
// Device scratch (static allocation — the sanctioned workaround, no cudaMalloc)
// ---------------------------------------------------------------------------
__device__ float g_Wl  [DDIM*DDIM];            // folded wq@kv  (logit weights, scale folded)
__device__ float g_P   [DDIM*DDIM];            // folded kv@wo  (latent->D projection)
__device__ float g_Q1  [DDIM*DDIM];            // P @ w1
__device__ float g_attn[(size_t)NTOK*DDIM];    // softmax(attn) [N,1024]  (512 MB)
__device__ float g_Gsum[BATCH*DDIM];           // per-batch column sums of gelu(...)
__device__ float g_Asum[BATCH*DDIM];           // per-batch column sums of attn

// ---------------------------------------------------------------------------
// k_zero: clear accumulators (graph replays must start clean)
// ---------------------------------------------------------------------------
__global__ void k_zero(float* __restrict__ G, float* __restrict__ A) {
    int i = blockIdx.x * blockDim.x + threadIdx.x;
    if (i < BATCH*DDIM) { G[i] = 0.f; A[i] = 0.f; }
}

// ---------------------------------------------------------------------------
// k_wl: W_l[d, h*R+r] = SCALE * sum_t wq[d, h*64+t] * kvl[r, h*64+t]
// grid (1024 d, 16 h), 64 threads: one r each. kv segment staged in smem.
// ---------------------------------------------------------------------------
__global__ void k_wl(const float* __restrict__ wq, const float* __restrict__ kvl,
                     float* __restrict__ Wl) {
    __shared__ float kvs[64][65];   // [r][t], padded
    __shared__ float wseg[64];
    int d = blockIdx.x, h = blockIdx.y;
    int tid = threadIdx.x;          // 64 threads
    // load kv segment: row r = tid, 64 floats
    for (int t = 0; t < 64; t++)
        kvs[tid][t] = kvl[(size_t)tid*DDIM + h*HD + t];
    wseg[tid] = wq[(size_t)d*DDIM + h*HD + tid];
    __syncthreads();
    int r = tid;
    float s = 0.f;
    #pragma unroll
    for (int t = 0; t < 64; t++) s += wseg[t] * kvs[r][t];
    Wl[(size_t)d*DDIM + h*RLAT + r] = s * SCALE;
}

// ---------------------------------------------------------------------------
// k_p: P[j=(h*R+r), e] = sum_t kvl[r, h*64+t] * wo[h*64+t, e]
// grid 1024 (one j per block), 256 threads over e (4 each)
// ---------------------------------------------------------------------------
__global__ void k_p(const float* __restrict__ kvl, const float* __restrict__ wo,
                    float* __restrict__ P) {
    __shared__ float kv_s[HD];
    int j = blockIdx.x, h = j >> 6, r = j & 63;
    if (threadIdx.x < HD) kv_s[threadIdx.x] = kvl[(size_t)r*DDIM + h*HD + threadIdx.x];
    __syncthreads();
    float acc[4] = {0.f, 0.f, 0.f, 0.f};
    for (int t = 0; t < HD; t++) {
        float kvv = kv_s[t];
        const float* worow = wo + (size_t)(h*HD + t)*DDIM;
        #pragma unroll
        for (int ee = 0; ee < 4; ee++)
            acc[ee] += kvv * worow[threadIdx.x + 256*ee];
    }
    #pragma unroll
    for (int ee = 0; ee < 4; ee++)
        P[(size_t)j*DDIM + threadIdx.x + 256*ee] = acc[ee];
}

// ---------------------------------------------------------------------------
// gemm128<MODE>: C_tile[128x128] = A[M,1024] @ B[1024,1024] tile
//   MODE 0: plain store to C                    (used for Q1 = P @ w1)
//   MODE 1: per-head softmax + store attn + per-batch column sums (A_sum)
//   MODE 2: +b1, exact gelu, per-batch column sums (G_sum); nothing stored
// 256 threads, 8x8 microtile per thread, K-chunk 16, dynamic smem 64KB.
// ---------------------------------------------------------------------------
template<int MODE>
__global__ void __launch_bounds__(256)
gemm128(const float* __restrict__ A, const float* __restrict__ B,
        const float* __restrict__ bias, float* __restrict__ C,
        float* __restrict__ attn_out, float* __restrict__ red_out) {
    extern __shared__ float sh[];
    float* As = sh;               // [16][128]  k-major
    float* Bs = sh + 16*128;      // [16][128]

    const int tid = threadIdx.x;
    const int tx = tid & 15, ty = tid >> 4;
    const int row0 = blockIdx.y * 128, col0 = blockIdx.x * 128;

    float acc[8][8];
    #pragma unroll
    for (int i = 0; i < 8; i++)
        #pragma unroll
        for (int j = 0; j < 8; j++) acc[i][j] = 0.f;

    for (int kc = 0; kc < DDIM; kc += 16) {
        // A tile 128x16 -> As[k][m]
        #pragma unroll
        for (int i = 0; i < 2; i++) {
            int f = tid + i*256;
            int m = f >> 2, k4 = (f & 3) * 4;
            float4 v = *(const float4*)(A + (size_t)(row0+m)*DDIM + kc + k4);
            As[(k4+0)*128 + m] = v.x;
            As[(k4+1)*128 + m] = v.y;
            As[(k4+2)*128 + m] = v.z;
            As[(k4+3)*128 + m] = v.w;
        }
        // B tile 16x128 -> Bs[k][n]
        #pragma unroll
        for (int i = 0; i < 2; i++) {
            int f = tid + i*256;
            int k = f >> 5, n4 = (f & 31) * 4;
            *(float4*)(Bs + k*128 + n4) =
                *(const float4*)(B + (size_t)(kc+k)*DDIM + col0 + n4);
        }
        __syncthreads();
        #pragma unroll
        for (int kk = 0; kk < 16; kk++) {
            float a[8], b[8];
            *(float4*)(a  ) = *(const float4*)(As + kk*128 + ty*8);
            *(float4*)(a+4) = *(const float4*)(As + kk*128 + ty*8 + 4);
            *(float4*)(b  ) = *(const float4*)(Bs + kk*128 + tx*8);
            *(float4*)(b+4) = *(const float4*)(Bs + kk*128 + tx*8 + 4);
            #pragma unroll
            for (int i = 0; i < 8; i++)
                #pragma unroll
                for (int j = 0; j < 8; j++)
                    acc[i][j] = fmaf(a[i], b[j], acc[i][j]);
        }
        __syncthreads();
    }

    if constexpr (MODE == 0) {
        #pragma unroll
        for (int i = 0; i < 8; i++) {
            *(float4*)(C + (size_t)(row0+ty*8+i)*DDIM + col0 + tx*8) =
                make_float4(acc[i][0], acc[i][1], acc[i][2], acc[i][3]);
            *(float4*)(C + (size_t)(row0+ty*8+i)*DDIM + col0 + tx*8 + 4) =
                make_float4(acc[i][4], acc[i][5], acc[i][6], acc[i][7]);
        }
    }

    if constexpr (MODE == 1) {
        // Stage C tile in smem (reuses As/Bs region; safe after trailing sync)
        float* Cs = sh;   // [128][128]
        #pragma unroll
        for (int i = 0; i < 8; i++) {
            *(float4*)(Cs + (ty*8+i)*128 + tx*8) =
                make_float4(acc[i][0], acc[i][1], acc[i][2], acc[i][3]);
            *(float4*)(Cs + (ty*8+i)*128 + tx*8 + 4) =
                make_float4(acc[i][4], acc[i][5], acc[i][6], acc[i][7]);
        }
        __syncthreads();
        // softmax: one (row, 64-col head chunk) per thread; staggered to
        // avoid smem bank conflicts
        {
            int lane = tid & 31;
            float* rowp = Cs + (tid >> 1)*128 + (tid & 1)*64;
            float mx = -CUDART_INF_F;
            #pragma unroll
            for (int t = 0; t < 64; t++) {
                int c = (t + lane) & 63;
                mx = fmaxf(mx, rowp[c]);
            }
            float s = 0.f;
            #pragma unroll
            for (int t = 0; t < 64; t++) {
                int c = (t + lane) & 63;
                float e = expf(rowp[c] - mx);
                rowp[c] = e;
                s += e;
            }
            float inv = 1.f / s;
            #pragma unroll
            for (int t = 0; t < 64; t++) {
                int c = (t + lane) & 63;
                rowp[c] *= inv;
            }
        }
        __syncthreads();
        // write attn tile (coalesced)
        #pragma unroll
        for (int i = 0; i < 16; i++) {
            int f = tid + i*256;
            int r = f >> 5, c4 = (f & 31) * 4;
            *(float4*)(attn_out + (size_t)(row0+r)*DDIM + col0 + c4) =
                *(const float4*)(Cs + r*128 + c4);
        }
        // per-batch column sums of attn
        if (tid < 128) {
            float s = 0.f;
            #pragma unroll 8
            for (int r = 0; r < 128; r++) s += Cs[r*128 + tid];
            int batch = row0 / SEQ;   // 128-row tiles never straddle batches
            atomicAdd(&red_out[batch*DDIM + col0 + tid], s);
        }
    }

    if constexpr (MODE == 2) {
        float bl[8];
        #pragma unroll
        for (int j = 0; j < 8; j++) bl[j] = bias[col0 + tx*8 + j];
        float cs[8];
        #pragma unroll
        for (int j = 0; j < 8; j++) cs[j] = 0.f;
        #pragma unroll
        for (int i = 0; i < 8; i++)
            #pragma unroll
            for (int j = 0; j < 8; j++) {
                float z = acc[i][j] + bl[j];
                float g = 0.5f * z * (1.f + erff(z * 0.70710678118654752f));
                cs[j] += g;
            }
        // reduce 16 ty-groups per column via smem (reuses As/Bs region)
        #pragma unroll
        for (int j = 0; j < 8; j++) sh[ty*128 + tx*8 + j] = cs[j];
        __syncthreads();
        if (tid < 128) {
            float s = 0.f;
            #pragma unroll
            for (int t = 0; t < 16; t++) s += sh[t*128 + tid];
            int batch = row0 / SEQ;
            atomicAdd(&red_out[batch*DDIM + col0 + tid], s);
        }
    }
}

// ---------------------------------------------------------------------------
// k_final: out[b,e] = b2[e] + (Gsum[b]/S) @ w2[:,e] + (Asum[b]/S) @ P[:,e]
// grid (4, 32), 256 threads
// ---------------------------------------------------------------------------
__global__ void k_final(const float* __restrict__ w2, const float* __restrict__ b2,
                        const float* __restrict__ Gsum, const float* __restrict__ Asum,
                        const float* __restrict__ P, float* __restrict__ out) {
    int b = blockIdx.y;
    int e = blockIdx.x * 256 + threadIdx.x;
    __shared__ float gs[DDIM], as[DDIM];
    const float invS = 1.f / (float)SEQ;
    for (int i = threadIdx.x; i < DDIM; i += 256) {
        gs[i] = Gsum[b*DDIM + i] * invS;
        as[i] = Asum[b*DDIM + i] * invS;
    }
    __syncthreads();
    float a0 = 0.f, a1 = 0.f, a2 = 0.f, a3 = 0.f;
    for (int k = 0; k < DDIM; k += 4) {
        a0 = fmaf(gs[k  ], w2[(size_t)(k  )*DDIM + e], fmaf(as[k  ], P[(size_t)(k  )*DDIM + e], a0));
        a1 = fmaf(gs[k+1], w2[(size_t)(k+1)*DDIM + e], fmaf(as[k+1], P[(size_t)(k+1)*DDIM + e], a1));
        a2 = fmaf(gs[k+2], w2[(size_t)(k+2)*DDIM + e], fmaf(as[k+2], P[(size_t)(k+2)*DDIM + e], a2));
        a3 = fmaf(gs[k+3], w2[(size_t)(k+3)*DDIM + e], fmaf(as[k+3], P[(size_t)(k+3)*DDIM + e], a3));
    }
    out[b*DDIM + e] = b2[e] + ((a0 + a1) + (a2 + a3));
}

// ---------------------------------------------------------------------------
// Host launcher
// ---------------------------------------------------------------------------
extern "C" void kernel_launch(void* const* d_in, const int* in_sizes, int n_in,
                              void* d_out, int out_size) {
    const float* x   = (const float*)d_in[0];
    const float* wq  = (const float*)d_in[1];
    const float* kvl = (const float*)d_in[2];
    const float* wo  = (const float*)d_in[3];
    const float* w1  = (const float*)d_in[4];
    const float* b1  = (const float*)d_in[5];
    const float* w2  = (const float*)d_in[6];
    const float* b2  = (const float*)d_in[7];
    float* out = (float*)d_out;

    float *pWl, *pP, *pQ1, *pAttn, *pG, *pA;
    cudaGetSymbolAddress((void**)&pWl,   g_Wl);
    cudaGetSymbolAddress((void**)&pP,    g_P);
    cudaGetSymbolAddress((void**)&pQ1,   g_Q1);
    cudaGetSymbolAddress((void**)&pAttn, g_attn);
    cudaGetSymbolAddress((void**)&pG,    g_Gsum);
    cudaGetSymbolAddress((void**)&pA,    g_Asum);

    const int SMEM = 65536;  // 64 KB dynamic
    cudaFuncSetAttribute(gemm128<0>, cudaFuncAttributeMaxDynamicSharedMemorySize, SMEM);
    cudaFuncSetAttribute(gemm128<1>, cudaFuncAttributeMaxDynamicSharedMemorySize, SMEM);
    cudaFuncSetAttribute(gemm128<2>, cudaFuncAttributeMaxDynamicSharedMemorySize, SMEM);

    // 1. zero accumulators
    k_zero<<<(BATCH*DDIM + 255)/256, 256>>>(pG, pA);
    // 2. precompute folded weights
    k_wl<<<dim3(DDIM, NHEAD), 64>>>(wq, kvl, pWl);
    k_p <<<DDIM, 256>>>(kvl, wo, pP);
    // 3. Q1 = P @ w1   [1024x1024x1024]
    gemm128<0><<<dim3(8, 8), 256, SMEM>>>(pP, w1, nullptr, pQ1, nullptr, nullptr);
    // 4. attn = softmax(x @ W_l) ; A_sum accumulated   [131072x1024x1024]
    gemm128<1><<<dim3(8, NTOK/128), 256, SMEM>>>(x, pWl, nullptr, nullptr, pAttn, pA);
    // 5. G_sum += colsum(gelu(attn @ Q1 + b1))         [131072x1024x1024]
    gemm128<2><<<dim3(8, NTOK/128), 256, SMEM>>>(pAttn, pQ1, b1, nullptr, nullptr, pG);
    // 6. final tiny GEMMs + bias + residual mean
    k_final<<<dim3(4, BATCH), 256>>>(w2, b2, pG, pA, pP, out);
}

// round 5
// speedup vs baseline: 2.2389x; 2.2389x over previous
#include <cuda_runtime.h>
#include <cuda_bf16.h>
#include <cstdint>
#include <stdint.h>
#include <math.h>
#include <math_constants.h>

// Problem constants
#define BATCH  32
#define SEQ    4096
#define DDIM   1024
#define NTOK   (BATCH*SEQ)     // 131072
#define NHEAD  16
#define HD     64
#define RLAT   64
#define SCALE  0.125f          // R^-0.5

// ---------------------------------------------------------------------------
// Device scratch (static allocation; no cudaMalloc allowed)
// ---------------------------------------------------------------------------
__device__ float g_Wl  [DDIM*DDIM];            // folded wq@kv (scale folded)
__device__ float g_P   [DDIM*DDIM];            // folded kv@wo
__device__ float g_Q1  [DDIM*DDIM];            // P @ w1
__device__ __nv_bfloat16 g_B1h[DDIM*DDIM];     // Wl^T  hi  (n-major, k contiguous)
__device__ __nv_bfloat16 g_B1l[DDIM*DDIM];     // Wl^T  lo
__device__ __nv_bfloat16 g_B2h[DDIM*DDIM];     // Q1^T  hi
__device__ __nv_bfloat16 g_B2l[DDIM*DDIM];     // Q1^T  lo
__device__ float g_attn[(size_t)NTOK*DDIM];    // softmax(attn) fp32 (512 MB)
__device__ float g_Gsum[BATCH*DDIM];
__device__ float g_Asum[BATCH*DDIM];

// ---------------------------------------------------------------------------
// Portable PTX helpers (sm_80+ ISA only — harness emits compute_103 PTX,
// so NO tcgen05/TMA arch-specific instructions are available)
// ---------------------------------------------------------------------------
__device__ __forceinline__ uint32_t smem_u32(const void* p) {
    uint32_t a;
    asm("{ .reg .u64 t; cvta.to.shared.u64 t, %1; cvt.u32.u64 %0, t; }" : "=r"(a) : "l"(p));
    return a;
}
__device__ __forceinline__ void ldm_x4(uint32_t* r, uint32_t a) {
    asm volatile("ldmatrix.sync.aligned.m8n8.x4.shared.b16 {%0,%1,%2,%3}, [%4];"
        : "=r"(r[0]), "=r"(r[1]), "=r"(r[2]), "=r"(r[3]) : "r"(a));
}
__device__ __forceinline__ void ldm_x2(uint32_t* r, uint32_t a) {
    asm volatile("ldmatrix.sync.aligned.m8n8.x2.shared.b16 {%0,%1}, [%2];"
        : "=r"(r[0]), "=r"(r[1]) : "r"(a));
}
__device__ __forceinline__ void mma16816(float* c, const uint32_t* a, const uint32_t* b) {
    asm volatile("mma.sync.aligned.m16n8k16.row.col.f32.bf16.bf16.f32 "
        "{%0,%1,%2,%3}, {%4,%5,%6,%7}, {%8,%9}, {%0,%1,%2,%3};"
        : "+f"(c[0]), "+f"(c[1]), "+f"(c[2]), "+f"(c[3])
        : "r"(a[0]), "r"(a[1]), "r"(a[2]), "r"(a[3]), "r"(b[0]), "r"(b[1]));
}
#define CP_ASYNC16(dst, src) \
    asm volatile("cp.async.cg.shared.global [%0], [%1], 16;" :: "r"(dst), "l"(src) : "memory")
#define CP_COMMIT() asm volatile("cp.async.commit_group;" ::: "memory")
#define CP_WAIT0()  asm volatile("cp.async.wait_group 0;" ::: "memory")

// 16B-unit XOR swizzle: row stride 64B (BK=32 bf16), unit u in 0..3
__device__ __forceinline__ int swz(int row, int u) {
    return row * 64 + ((u ^ ((row >> 1) & 3)) << 4);
}

// ---------------------------------------------------------------------------
// wm_gemm<MODE>: C[128x128] = split_bf16(A fp32) @ (Bhi,Blo)   via mma.sync
//   MODE 1: per-head softmax (64-col groups), store attn fp32, colsum -> red
//   MODE 2: +bias, exact gelu, colsum -> red (nothing stored)
// 256 threads = 8 warps (2 M-halves x 4 N-quarters), warp tile 64x32.
// Stage: A hi/lo 16KB + B hi/lo 16KB = 32KB, double buffered.
// ---------------------------------------------------------------------------
#define NKC      32            // K chunks of 32
#define STG      32768         // bytes per stage
#define OFF_AL   8192
#define OFF_B    16384
#define OFF_BL   24576
#define WG_SMEM  67584         // 128*132*4 (epilogue Cs) >= 2*STG

template<int MODE>
__global__ void __launch_bounds__(256, 1)
wm_gemm(const float* __restrict__ A,
        const __nv_bfloat16* __restrict__ Bhi, const __nv_bfloat16* __restrict__ Blo,
        const float* __restrict__ bias,
        float* __restrict__ outF, float* __restrict__ redOut)
{
    extern __shared__ char sm[];
    const uint32_t smb = smem_u32(sm);
    const int tid = threadIdx.x;
    const int lane = tid & 31, wid = tid >> 5;
    const int wm = wid & 1;                    // warp M half (0/1)
    const int wncol = (wid >> 1) * 32;         // warp N base col
    const int row0 = blockIdx.y * 128, col0 = blockIdx.x * 128;

    float acc[4][4][4];
    #pragma unroll
    for (int i = 0; i < 4; i++)
        #pragma unroll
        for (int j = 0; j < 4; j++)
            #pragma unroll
            for (int r = 0; r < 4; r++) acc[i][j][r] = 0.f;

    // per-thread staging unit coords (2 units each for A-src, B-hi, B-lo)
    const int u0r = (tid + 0)   >> 2, u0u = (tid + 0)   & 3;
    const int u1r = (tid + 256) >> 2, u1u = (tid + 256) & 3;

    // ---- B loader (cp.async, 16B units) into stage s for chunk kc
    auto loadB = [&](int kc, int s) {
        uint32_t base = smb + s * STG;
        const __nv_bfloat16* bh0 = Bhi + (size_t)(col0 + u0r) * DDIM + kc * 32 + u0u * 8;
        const __nv_bfloat16* bh1 = Bhi + (size_t)(col0 + u1r) * DDIM + kc * 32 + u1u * 8;
        const __nv_bfloat16* bl0 = Blo + (size_t)(col0 + u0r) * DDIM + kc * 32 + u0u * 8;
        const __nv_bfloat16* bl1 = Blo + (size_t)(col0 + u1r) * DDIM + kc * 32 + u1u * 8;
        CP_ASYNC16(base + OFF_B  + swz(u0r, u0u), bh0);
        CP_ASYNC16(base + OFF_B  + swz(u1r, u1u), bh1);
        CP_ASYNC16(base + OFF_BL + swz(u0r, u0u), bl0);
        CP_ASYNC16(base + OFF_BL + swz(u1r, u1u), bl1);
    };
    // ---- A loader: 2 units x 8 fp32 into regs
    auto loadA = [&](int kc, float4* av) {
        const float* a0 = A + (size_t)(row0 + u0r) * DDIM + kc * 32 + u0u * 8;
        const float* a1 = A + (size_t)(row0 + u1r) * DDIM + kc * 32 + u1u * 8;
        av[0] = *(const float4*)(a0);
        av[1] = *(const float4*)(a0 + 4);
        av[2] = *(const float4*)(a1);
        av[3] = *(const float4*)(a1 + 4);
    };
    // ---- A convert + STS (hi 16B + lo 16B per unit)
    auto stsA = [&](const float4* av, int s) {
        char* base = sm + (size_t)s * STG;
        #pragma unroll
        for (int i = 0; i < 2; i++) {
            float4 v0 = av[2*i], v1 = av[2*i+1];
            __nv_bfloat162 h0 = __floats2bfloat162_rn(v0.x, v0.y);
            __nv_bfloat162 h1 = __floats2bfloat162_rn(v0.z, v0.w);
            __nv_bfloat162 h2 = __floats2bfloat162_rn(v1.x, v1.y);
            __nv_bfloat162 h3 = __floats2bfloat162_rn(v1.z, v1.w);
            __nv_bfloat162 l0 = __floats2bfloat162_rn(v0.x - __bfloat162float(h0.x), v0.y - __bfloat162float(h0.y));
            __nv_bfloat162 l1 = __floats2bfloat162_rn(v0.z - __bfloat162float(h1.x), v0.w - __bfloat162float(h1.y));
            __nv_bfloat162 l2 = __floats2bfloat162_rn(v1.x - __bfloat162float(h2.x), v1.y - __bfloat162float(h2.y));
            __nv_bfloat162 l3 = __floats2bfloat162_rn(v1.z - __bfloat162float(h3.x), v1.w - __bfloat162float(h3.y));
            int r = i ? u1r : u0r, u = i ? u1u : u0u;
            uint4 hv = make_uint4(*(uint32_t*)&h0, *(uint32_t*)&h1, *(uint32_t*)&h2, *(uint32_t*)&h3);
            uint4 lv = make_uint4(*(uint32_t*)&l0, *(uint32_t*)&l1, *(uint32_t*)&l2, *(uint32_t*)&l3);
            *(uint4*)(base + swz(r, u))          = hv;
            *(uint4*)(base + OFF_AL + swz(r, u)) = lv;
        }
    };

    // ---- prologue: chunk 0
    loadB(0, 0); CP_COMMIT();
    { float4 av[4]; loadA(0, av); stsA(av, 0); }
    CP_WAIT0(); __syncthreads();

    // ---- main loop
    for (int kc = 0; kc < NKC; kc++) {
        const int cur = kc & 1;
        float4 av[4];
        if (kc < NKC - 1) { loadB(kc + 1, cur ^ 1); CP_COMMIT(); loadA(kc + 1, av); }

        const uint32_t sA = smb + cur * STG;
        const uint32_t sB = sA + OFF_B;
        #pragma unroll
        for (int kk = 0; kk < 2; kk++) {
            uint32_t ah[4][4], al[4][4], bh[4][2], bl[4][2];
            #pragma unroll
            for (int mt = 0; mt < 4; mt++) {
                int arow = wm * 64 + mt * 16 + (lane & 7) + ((lane >> 3) & 1) * 8;
                int au   = kk * 2 + (lane >> 4);
                uint32_t ad = sA + swz(arow, au);
                ldm_x4(ah[mt], ad);
                ldm_x4(al[mt], ad + OFF_AL);
            }
            #pragma unroll
            for (int nt = 0; nt < 4; nt++) {
                int l16  = lane & 15;
                int brow = wncol + nt * 8 + (l16 & 7);
                int bu   = kk * 2 + (l16 >> 3);
                uint32_t bd = sB + swz(brow, bu);
                ldm_x2(bh[nt], bd);
                ldm_x2(bl[nt], bd + 8192);
            }
            #pragma unroll
            for (int mt = 0; mt < 4; mt++)
                #pragma unroll
                for (int nt = 0; nt < 4; nt++) {
                    mma16816(acc[mt][nt], ah[mt], bh[nt]);
                    mma16816(acc[mt][nt], ah[mt], bl[nt]);
                    mma16816(acc[mt][nt], al[mt], bh[nt]);
                }
        }
        if (kc < NKC - 1) stsA(av, cur ^ 1);
        CP_WAIT0(); __syncthreads();
    }

    const int batch = row0 >> 12;   // SEQ = 4096

    if (MODE == 1) {
        // stage C tile to smem (stride 132 floats: float4-aligned rows)
        float* Cs = (float*)sm;
        #pragma unroll
        for (int mt = 0; mt < 4; mt++)
            #pragma unroll
            for (int nt = 0; nt < 4; nt++) {
                int row = wm * 64 + mt * 16 + (lane >> 2);
                int col = wncol + nt * 8 + (lane & 3) * 2;
                *(float2*)&Cs[row * 132 + col]       = make_float2(acc[mt][nt][0], acc[mt][nt][1]);
                *(float2*)&Cs[(row + 8) * 132 + col] = make_float2(acc[mt][nt][2], acc[mt][nt][3]);
            }
        __syncthreads();
        // per-thread softmax over one 64-latent head segment
        const int r = tid >> 1, hf = tid & 1;
        float f[64];
        #pragma unroll
        for (int j = 0; j < 16; j++)
            *(float4*)&f[j * 4] = *(const float4*)&Cs[r * 132 + hf * 64 + j * 4];
        float mx = -CUDART_INF_F;
        #pragma unroll
        for (int j = 0; j < 64; j++) mx = fmaxf(mx, f[j]);
        float s = 0.f;
        #pragma unroll
        for (int j = 0; j < 64; j++) { f[j] = __expf(f[j] - mx); s += f[j]; }
        float inv = 1.f / s;
        #pragma unroll
        for (int j = 0; j < 64; j++) f[j] *= inv;
        // store attn fp32
        float* dst = outF + (size_t)(row0 + r) * DDIM + col0 + hf * 64;
        #pragma unroll
        for (int j = 0; j < 16; j++)
            *(float4*)(dst + j * 4) = make_float4(f[4*j], f[4*j+1], f[4*j+2], f[4*j+3]);
        __syncthreads();           // all Cs reads done; reuse as red[col][row]
        float* red = (float*)sm;
        #pragma unroll
        for (int j = 0; j < 64; j++) red[(hf * 64 + j) * 129 + r] = f[j];
        __syncthreads();
        if (tid < 128) {
            float s2 = 0.f;
            #pragma unroll 8
            for (int rr = 0; rr < 128; rr++) s2 += red[tid * 129 + rr];
            atomicAdd(&redOut[batch * DDIM + col0 + tid], s2);
        }
    }

    if (MODE == 2) {
        float bv[4][2];
        #pragma unroll
        for (int nt = 0; nt < 4; nt++)
            #pragma unroll
            for (int p = 0; p < 2; p++)
                bv[nt][p] = __ldg(&bias[col0 + wncol + nt * 8 + (lane & 3) * 2 + p]);
        float cs[4][2];
        #pragma unroll
        for (int nt = 0; nt < 4; nt++) { cs[nt][0] = 0.f; cs[nt][1] = 0.f; }
        #pragma unroll
        for (int mt = 0; mt < 4; mt++)
            #pragma unroll
            for (int nt = 0; nt < 4; nt++)
                #pragma unroll
                for (int rg = 0; rg < 4; rg++) {
                    float z = acc[mt][nt][rg] + bv[nt][rg & 1];
                    float g = 0.5f * z * (1.f + erff(z * 0.70710678118654752f));
                    cs[nt][rg & 1] += g;
                }
        float* red = (float*)sm;   // [128 cols][17 slots]
        const int slot = wm * 8 + (lane >> 2);
        __syncthreads();
        #pragma unroll
        for (int nt = 0; nt < 4; nt++)
            #pragma unroll
            for (int p = 0; p < 2; p++)
                red[(wncol + nt * 8 + (lane & 3) * 2 + p) * 17 + slot] = cs[nt][p];
        __syncthreads();
        if (tid < 128) {
            float s2 = 0.f;
            #pragma unroll
            for (int t = 0; t < 16; t++) s2 += red[tid * 17 + t];
            atomicAdd(&redOut[batch * DDIM + col0 + tid], s2);
        }
    }
}

// ---------------------------------------------------------------------------
// k_zero
// ---------------------------------------------------------------------------
__global__ void k_zero(float* __restrict__ G, float* __restrict__ A) {
    int i = blockIdx.x * blockDim.x + threadIdx.x;
    if (i < BATCH*DDIM) { G[i] = 0.f; A[i] = 0.f; }
}

// ---------------------------------------------------------------------------
// k_wl: W_l[d, h*R+r] = SCALE * sum_t wq[d, h*64+t] * kvl[r, h*64+t]
// ---------------------------------------------------------------------------
__global__ void k_wl(const float* __restrict__ wq, const float* __restrict__ kvl,
                     float* __restrict__ Wl) {
    __shared__ float kvs[64][65];
    __shared__ float wseg[64];
    int d = blockIdx.x, h = blockIdx.y;
    int tid = threadIdx.x;
    for (int t = 0; t < 64; t++)
        kvs[tid][t] = kvl[(size_t)tid*DDIM + h*HD + t];
    wseg[tid] = wq[(size_t)d*DDIM + h*HD + tid];
    __syncthreads();
    float s = 0.f;
    #pragma unroll
    for (int t = 0; t < 64; t++) s += wseg[t] * kvs[tid][t];
    Wl[(size_t)d*DDIM + h*RLAT + tid] = s * SCALE;
}

// ---------------------------------------------------------------------------
// k_p: P[j=(h*R+r), e] = sum_t kvl[r, h*64+t] * wo[h*64+t, e]
// ---------------------------------------------------------------------------
__global__ void k_p(const float* __restrict__ kvl, const float* __restrict__ wo,
                    float* __restrict__ P) {
    __shared__ float kv_s[HD];
    int j = blockIdx.x, h = j >> 6, r = j & 63;
    if (threadIdx.x < HD) kv_s[threadIdx.x] = kvl[(size_t)r*DDIM + h*HD + threadIdx.x];
    __syncthreads();
    float acc[4] = {0.f, 0.f, 0.f, 0.f};
    for (int t = 0; t < HD; t++) {
        float kvv = kv_s[t];
        const float* worow = wo + (size_t)(h*HD + t)*DDIM;
        #pragma unroll
        for (int ee = 0; ee < 4; ee++)
            acc[ee] += kvv * worow[threadIdx.x + 256*ee];
    }
    #pragma unroll
    for (int ee = 0; ee < 4; ee++)
        P[(size_t)j*DDIM + threadIdx.x + 256*ee] = acc[ee];
}

// ---------------------------------------------------------------------------
// gemm1k: fp32 SIMT GEMM for Q1 = P @ w1 (small: 1024^3)
// ---------------------------------------------------------------------------
__global__ void __launch_bounds__(256)
gemm1k(const float* __restrict__ A, const float* __restrict__ B, float* __restrict__ C) {
    extern __shared__ float sh[];
    float* As = sh;               // [16][128]
    float* Bs = sh + 16*128;
    const int tid = threadIdx.x;
    const int tx = tid & 15, ty = tid >> 4;
    const int row0 = blockIdx.y * 128, col0 = blockIdx.x * 128;
    float acc[8][8];
    #pragma unroll
    for (int i = 0; i < 8; i++)
        #pragma unroll
        for (int j = 0; j < 8; j++) acc[i][j] = 0.f;
    for (int kcb = 0; kcb < DDIM; kcb += 16) {
        #pragma unroll
        for (int i = 0; i < 2; i++) {
            int f = tid + i*256;
            int m = f >> 2, k4 = (f & 3) * 4;
            float4 v = *(const float4*)(A + (size_t)(row0+m)*DDIM + kcb + k4);
            As[(k4+0)*128 + m] = v.x; As[(k4+1)*128 + m] = v.y;
            As[(k4+2)*128 + m] = v.z; As[(k4+3)*128 + m] = v.w;
        }
        #pragma unroll
        for (int i = 0; i < 2; i++) {
            int f = tid + i*256;
            int k = f >> 5, n4 = (f & 31) * 4;
            *(float4*)(Bs + k*128 + n4) = *(const float4*)(B + (size_t)(kcb+k)*DDIM + col0 + n4);
        }
        __syncthreads();
        #pragma unroll
        for (int kk = 0; kk < 16; kk++) {
            float a[8], b[8];
            *(float4*)(a  ) = *(const float4*)(As + kk*128 + ty*8);
            *(float4*)(a+4) = *(const float4*)(As + kk*128 + ty*8 + 4);
            *(float4*)(b  ) = *(const float4*)(Bs + kk*128 + tx*8);
            *(float4*)(b+4) = *(const float4*)(Bs + kk*128 + tx*8 + 4);
            #pragma unroll
            for (int i = 0; i < 8; i++)
                #pragma unroll
                for (int j = 0; j < 8; j++)
                    acc[i][j] = fmaf(a[i], b[j], acc[i][j]);
        }
        __syncthreads();
    }
    #pragma unroll
    for (int i = 0; i < 8; i++) {
        *(float4*)(C + (size_t)(row0+ty*8+i)*DDIM + col0 + tx*8) =
            make_float4(acc[i][0], acc[i][1], acc[i][2], acc[i][3]);
        *(float4*)(C + (size_t)(row0+ty*8+i)*DDIM + col0 + tx*8 + 4) =
            make_float4(acc[i][4], acc[i][5], acc[i][6], acc[i][7]);
    }
}

// ---------------------------------------------------------------------------
// k_prepB: B[n][k] = split_bf16(W[k][n])  (transpose + hi/lo split)
// ---------------------------------------------------------------------------
__global__ void k_prepB(const float* __restrict__ W,
                        __nv_bfloat16* __restrict__ Bh, __nv_bfloat16* __restrict__ Bl) {
    __shared__ float t[32][33];
    int bx = blockIdx.x * 32, by = blockIdx.y * 32;
    int tx = threadIdx.x & 31, ty = threadIdx.x >> 5;  // 8 rows
    #pragma unroll
    for (int i = 0; i < 4; i++)
        t[ty + 8*i][tx] = W[(size_t)(by + ty + 8*i)*DDIM + bx + tx];
    __syncthreads();
    #pragma unroll
    for (int i = 0; i < 4; i++) {
        float v = t[tx][ty + 8*i];
        __nv_bfloat16 h = __float2bfloat16(v);
        __nv_bfloat16 l = __float2bfloat16(v - __bfloat162float(h));
        Bh[(size_t)(bx + ty + 8*i)*DDIM + by + tx] = h;
        Bl[(size_t)(bx + ty + 8*i)*DDIM + by + tx] = l;
    }
}

// ---------------------------------------------------------------------------
// k_final: out[b,e] = b2[e] + (Gsum[b]/S) @ w2[:,e] + (Asum[b]/S) @ P[:,e]
// ---------------------------------------------------------------------------
__global__ void k_final(const float* __restrict__ w2, const float* __restrict__ b2,
                        const float* __restrict__ Gsum, const float* __restrict__ Asum,
                        const float* __restrict__ P, float* __restrict__ out) {
    int b = blockIdx.y;
    int e = blockIdx.x * 256 + threadIdx.x;
    __shared__ float gs[DDIM], as[DDIM];
    const float invS = 1.f / (float)SEQ;
    for (int i = threadIdx.x; i < DDIM; i += 256) {
        gs[i] = Gsum[b*DDIM + i] * invS;
        as[i] = Asum[b*DDIM + i] * invS;
    }
    __syncthreads();
    float a0 = 0.f, a1 = 0.f, a2 = 0.f, a3 = 0.f;
    for (int k = 0; k < DDIM; k += 4) {
        a0 = fmaf(gs[k  ], w2[(size_t)(k  )*DDIM + e], fmaf(as[k  ], P[(size_t)(k  )*DDIM + e], a0));
        a1 = fmaf(gs[k+1], w2[(size_t)(k+1)*DDIM + e], fmaf(as[k+1], P[(size_t)(k+1)*DDIM + e], a1));
        a2 = fmaf(gs[k+2], w2[(size_t)(k+2)*DDIM + e], fmaf(as[k+2], P[(size_t)(k+2)*DDIM + e], a2));
        a3 = fmaf(gs[k+3], w2[(size_t)(k+3)*DDIM + e], fmaf(as[k+3], P[(size_t)(k+3)*DDIM + e], a3));
    }
    out[b*DDIM + e] = b2[e] + ((a0 + a1) + (a2 + a3));
}

// ---------------------------------------------------------------------------
// Host launcher
// ---------------------------------------------------------------------------
extern "C" void kernel_launch(void* const* d_in, const int* in_sizes, int n_in,
                              void* d_out, int out_size) {
    const float* x   = (const float*)d_in[0];
    const float* wq  = (const float*)d_in[1];
    const float* kvl = (const float*)d_in[2];
    const float* wo  = (const float*)d_in[3];
    const float* w1  = (const float*)d_in[4];
    const float* b1  = (const float*)d_in[5];
    const float* w2  = (const float*)d_in[6];
    const float* b2  = (const float*)d_in[7];
    float* out = (float*)d_out;

    float *pWl, *pP, *pQ1, *pAttn, *pG, *pA;
    __nv_bfloat16 *pB1h, *pB1l, *pB2h, *pB2l;
    cudaGetSymbolAddress((void**)&pWl,   g_Wl);
    cudaGetSymbolAddress((void**)&pP,    g_P);
    cudaGetSymbolAddress((void**)&pQ1,   g_Q1);
    cudaGetSymbolAddress((void**)&pAttn, g_attn);
    cudaGetSymbolAddress((void**)&pG,    g_Gsum);
    cudaGetSymbolAddress((void**)&pA,    g_Asum);
    cudaGetSymbolAddress((void**)&pB1h,  g_B1h);
    cudaGetSymbolAddress((void**)&pB1l,  g_B1l);
    cudaGetSymbolAddress((void**)&pB2h,  g_B2h);
    cudaGetSymbolAddress((void**)&pB2l,  g_B2l);

    cudaFuncSetAttribute(gemm1k,     cudaFuncAttributeMaxDynamicSharedMemorySize, 65536);
    cudaFuncSetAttribute(wm_gemm<1>, cudaFuncAttributeMaxDynamicSharedMemorySize, WG_SMEM);
    cudaFuncSetAttribute(wm_gemm<2>, cudaFuncAttributeMaxDynamicSharedMemorySize, WG_SMEM);

    // 1. zero accumulators
    k_zero<<<(BATCH*DDIM + 255)/256, 256>>>(pG, pA);
    // 2. folded weights
    k_wl<<<dim3(DDIM, NHEAD), 64>>>(wq, kvl, pWl);
    k_p <<<DDIM, 256>>>(kvl, wo, pP);
    // 3. Q1 = P @ w1 (fp32 SIMT, small)
    gemm1k<<<dim3(8, 8), 256, 65536>>>(pP, w1, pQ1);
    // 4. split-bf16 transposed weights
    k_prepB<<<dim3(32, 32), 256>>>(pWl, pB1h, pB1l);
    k_prepB<<<dim3(32, 32), 256>>>(pQ1, pB2h, pB2l);
    // 5. attn = softmax(x @ Wl); Asum accumulated  [mma.sync bf16 x3]
    wm_gemm<1><<<dim3(8, NTOK/128), 256, WG_SMEM>>>(x, pB1h, pB1l, nullptr, pAttn, pA);
    // 6. Gsum += colsum(gelu(attn @ Q1 + b1))       [mma.sync bf16 x3]
    wm_gemm<2><<<dim3(8, NTOK/128), 256, WG_SMEM>>>(pAttn, pB2h, pB2l, b1, nullptr, pG);
    // 7. final tiny GEMMs + bias + residual mean
    k_final<<<dim3(4, BATCH), 256>>>(w2, b2, pG, pA, pP, out);
}

// round 6
// speedup vs baseline: 2.9497x; 1.3175x over previous
#include <cuda_runtime.h>
#include <cuda_fp16.h>
#include <cstdint>
#include <stdint.h>
#include <math.h>
#include <math_constants.h>

// Problem constants
#define BATCH  32
#define SEQ    4096
#define DDIM   1024
#define NTOK   (BATCH*SEQ)     // 131072
#define NHEAD  16
#define HD     64
#define RLAT   64
#define SCALE  0.125f          // R^-0.5

// ---------------------------------------------------------------------------
// Device scratch (static allocation; no cudaMalloc allowed)
// ---------------------------------------------------------------------------
__device__ float g_Wl  [DDIM*DDIM];            // folded wq@kv (scale folded)
__device__ float g_P   [DDIM*DDIM];            // folded kv@wo
__device__ float g_Q1  [DDIM*DDIM];            // P @ w1
__device__ __half g_B1h[DDIM*DDIM];            // Wl^T  hi  (n-major, k contiguous)
__device__ __half g_B1l[DDIM*DDIM];            // Wl^T  lo
__device__ __half g_B2h[DDIM*DDIM];            // Q1^T  hi
__device__ __half g_B2l[DDIM*DDIM];            // Q1^T  lo
__device__ __half g_attnH[(size_t)NTOK*DDIM];  // softmax(attn) fp16 (256 MB)
__device__ float g_Gsum[BATCH*DDIM];
__device__ float g_Asum[BATCH*DDIM];

// ---------------------------------------------------------------------------
// Portable PTX helpers (sm_80+ ISA — harness emits compute_103 PTX, so no
// tcgen05/TMA arch-specific instructions are available)
// ---------------------------------------------------------------------------
__device__ __forceinline__ uint32_t smem_u32(const void* p) {
    uint32_t a;
    asm("{ .reg .u64 t; cvta.to.shared.u64 t, %1; cvt.u32.u64 %0, t; }" : "=r"(a) : "l"(p));
    return a;
}
__device__ __forceinline__ void ldm_x4(uint32_t* r, uint32_t a) {
    asm volatile("ldmatrix.sync.aligned.m8n8.x4.shared.b16 {%0,%1,%2,%3}, [%4];"
        : "=r"(r[0]), "=r"(r[1]), "=r"(r[2]), "=r"(r[3]) : "r"(a));
}
__device__ __forceinline__ void mma16816(float* c, const uint32_t* a, const uint32_t* b) {
    asm volatile("mma.sync.aligned.m16n8k16.row.col.f32.f16.f16.f32 "
        "{%0,%1,%2,%3}, {%4,%5,%6,%7}, {%8,%9}, {%0,%1,%2,%3};"
        : "+f"(c[0]), "+f"(c[1]), "+f"(c[2]), "+f"(c[3])
        : "r"(a[0]), "r"(a[1]), "r"(a[2]), "r"(a[3]), "r"(b[0]), "r"(b[1]));
}
#define CP_ASYNC16(dst, src) \
    asm volatile("cp.async.cg.shared.global [%0], [%1], 16;" :: "r"(dst), "l"(src) : "memory")
#define CP_COMMIT() asm volatile("cp.async.commit_group;" ::: "memory")
#define CP_WAIT0()  asm volatile("cp.async.wait_group 0;" ::: "memory")

// 16B-unit XOR swizzle: row stride 64B (BK=32 fp16), unit u in 0..3
__device__ __forceinline__ int swz(int row, int u) {
    return row * 64 + ((u ^ ((row >> 1) & 3)) << 4);
}

// ---------------------------------------------------------------------------
// wm_gemm<MODE, AHALF>: C[128x128] = A @ (Bhi + Blo)   [2-pass fp16 mma.sync]
//   A: fp32 (AHALF=0: LDG+convert+STS) or fp16 (AHALF=1: pure cp.async)
//   MODE 1: per-head softmax, store attn fp16, colsum -> redOut (Asum)
//   MODE 2: +bias, exact gelu, colsum -> redOut (Gsum); nothing stored
// 256 threads = 8 warps (2 M-halves x 4 N-quarters), warp tile 64x32, BK=32.
// Stage: A 8KB + Bh 8KB + Bl 8KB = 24KB, double buffered.
// ---------------------------------------------------------------------------
#define NKC      32            // K chunks of 32
#define STG      24576         // bytes per stage
#define OFF_BH   8192
#define OFF_BL   16384
#define WG_SMEM  67584         // epilogue Cs 128*132*4 >= 2*STG

template<int MODE, int AHALF>
__global__ void __launch_bounds__(256, 1)
wm_gemm(const float* __restrict__ Af, const __half* __restrict__ Ah16,
        const __half* __restrict__ Bhi, const __half* __restrict__ Blo,
        const float* __restrict__ bias,
        __half* __restrict__ attnOut, float* __restrict__ redOut)
{
    extern __shared__ char sm[];
    const uint32_t smb = smem_u32(sm);
    const int tid = threadIdx.x;
    const int lane = tid & 31, wid = tid >> 5;
    const int wm = wid & 1;                    // warp M half (0/1)
    const int wncol = (wid >> 1) * 32;         // warp N base col
    const int row0 = blockIdx.y * 128, col0 = blockIdx.x * 128;

    float acc[4][4][4];
    #pragma unroll
    for (int i = 0; i < 4; i++)
        #pragma unroll
        for (int j = 0; j < 4; j++)
            #pragma unroll
            for (int r = 0; r < 4; r++) acc[i][j][r] = 0.f;

    // per-thread staging unit coords (2 x 16B units per region)
    const int u0r = (tid + 0)   >> 2, u0u = (tid + 0)   & 3;
    const int u1r = (tid + 256) >> 2, u1u = (tid + 256) & 3;

    // ---- B loader (cp.async) into stage s for chunk kc
    auto loadB = [&](int kc, int s) {
        uint32_t base = smb + s * STG;
        CP_ASYNC16(base + OFF_BH + swz(u0r, u0u), Bhi + (size_t)(col0 + u0r) * DDIM + kc * 32 + u0u * 8);
        CP_ASYNC16(base + OFF_BH + swz(u1r, u1u), Bhi + (size_t)(col0 + u1r) * DDIM + kc * 32 + u1u * 8);
        CP_ASYNC16(base + OFF_BL + swz(u0r, u0u), Blo + (size_t)(col0 + u0r) * DDIM + kc * 32 + u0u * 8);
        CP_ASYNC16(base + OFF_BL + swz(u1r, u1u), Blo + (size_t)(col0 + u1r) * DDIM + kc * 32 + u1u * 8);
    };
    // ---- A loader, fp16 source (cp.async)
    auto loadA_async = [&](int kc, int s) {
        uint32_t base = smb + s * STG;
        CP_ASYNC16(base + swz(u0r, u0u), Ah16 + (size_t)(row0 + u0r) * DDIM + kc * 32 + u0u * 8);
        CP_ASYNC16(base + swz(u1r, u1u), Ah16 + (size_t)(row0 + u1r) * DDIM + kc * 32 + u1u * 8);
    };
    // ---- A loader, fp32 source: LDG into regs
    auto loadA_f32 = [&](int kc, float4* av) {
        const float* a0 = Af + (size_t)(row0 + u0r) * DDIM + kc * 32 + u0u * 8;
        const float* a1 = Af + (size_t)(row0 + u1r) * DDIM + kc * 32 + u1u * 8;
        av[0] = *(const float4*)(a0);
        av[1] = *(const float4*)(a0 + 4);
        av[2] = *(const float4*)(a1);
        av[3] = *(const float4*)(a1 + 4);
    };
    // ---- A convert + STS (fp32 -> fp16, 16B per unit)
    auto stsA = [&](const float4* av, int s) {
        char* base = sm + (size_t)s * STG;
        #pragma unroll
        for (int i = 0; i < 2; i++) {
            float4 v0 = av[2*i], v1 = av[2*i+1];
            __half2 h0 = __floats2half2_rn(v0.x, v0.y);
            __half2 h1 = __floats2half2_rn(v0.z, v0.w);
            __half2 h2 = __floats2half2_rn(v1.x, v1.y);
            __half2 h3 = __floats2half2_rn(v1.z, v1.w);
            int r = i ? u1r : u0r, u = i ? u1u : u0u;
            *(uint4*)(base + swz(r, u)) =
                make_uint4(*(uint32_t*)&h0, *(uint32_t*)&h1, *(uint32_t*)&h2, *(uint32_t*)&h3);
        }
    };

    // ---- prologue: chunk 0
    loadB(0, 0);
    if (AHALF) { loadA_async(0, 0); }
    CP_COMMIT();
    if (!AHALF) { float4 av[4]; loadA_f32(0, av); stsA(av, 0); }
    CP_WAIT0(); __syncthreads();

    // ---- main loop
    for (int kc = 0; kc < NKC; kc++) {
        const int cur = kc & 1;
        float4 av[4];
        if (kc < NKC - 1) {
            loadB(kc + 1, cur ^ 1);
            if (AHALF) loadA_async(kc + 1, cur ^ 1);
            CP_COMMIT();
            if (!AHALF) loadA_f32(kc + 1, av);
        }

        const uint32_t sA = smb + cur * STG;
        #pragma unroll
        for (int kk = 0; kk < 2; kk++) {
            uint32_t ah[4][4], bh[4][2], bl[4][2];
            #pragma unroll
            for (int mt = 0; mt < 4; mt++) {
                int arow = wm * 64 + mt * 16 + (lane & 7) + ((lane >> 3) & 1) * 8;
                int au   = kk * 2 + (lane >> 4);
                ldm_x4(ah[mt], sA + swz(arow, au));
            }
            #pragma unroll
            for (int nt2 = 0; nt2 < 2; nt2++) {
                // paired n-tiles: lanes 0-15 -> n-tile 2*nt2, lanes 16-31 -> 2*nt2+1
                int brow = wncol + nt2 * 16 + ((lane >> 4) << 3) + (lane & 7);
                int bu   = kk * 2 + ((lane >> 3) & 1);
                uint32_t r4[4];
                ldm_x4(r4, sA + OFF_BH + swz(brow, bu));
                bh[2*nt2][0] = r4[0]; bh[2*nt2][1] = r4[1];
                bh[2*nt2+1][0] = r4[2]; bh[2*nt2+1][1] = r4[3];
                ldm_x4(r4, sA + OFF_BL + swz(brow, bu));
                bl[2*nt2][0] = r4[0]; bl[2*nt2][1] = r4[1];
                bl[2*nt2+1][0] = r4[2]; bl[2*nt2+1][1] = r4[3];
            }
            #pragma unroll
            for (int mt = 0; mt < 4; mt++)
                #pragma unroll
                for (int nt = 0; nt < 4; nt++) {
                    mma16816(acc[mt][nt], ah[mt], bh[nt]);
                    mma16816(acc[mt][nt], ah[mt], bl[nt]);
                }
        }
        if (!AHALF && kc < NKC - 1) stsA(av, cur ^ 1);
        CP_WAIT0(); __syncthreads();
    }

    const int batch = row0 >> 12;   // SEQ = 4096

    if (MODE == 1) {
        // stage C tile to smem (stride 132 floats: float4-aligned rows)
        float* Cs = (float*)sm;
        #pragma unroll
        for (int mt = 0; mt < 4; mt++)
            #pragma unroll
            for (int nt = 0; nt < 4; nt++) {
                int row = wm * 64 + mt * 16 + (lane >> 2);
                int col = wncol + nt * 8 + (lane & 3) * 2;
                *(float2*)&Cs[row * 132 + col]       = make_float2(acc[mt][nt][0], acc[mt][nt][1]);
                *(float2*)&Cs[(row + 8) * 132 + col] = make_float2(acc[mt][nt][2], acc[mt][nt][3]);
            }
        __syncthreads();
        // per-thread softmax over one 64-latent head segment
        const int r = tid >> 1, hf = tid & 1;
        float f[64];
        #pragma unroll
        for (int j = 0; j < 16; j++)
            *(float4*)&f[j * 4] = *(const float4*)&Cs[r * 132 + hf * 64 + j * 4];
        float mx = -CUDART_INF_F;
        #pragma unroll
        for (int j = 0; j < 64; j++) mx = fmaxf(mx, f[j]);
        float s = 0.f;
        #pragma unroll
        for (int j = 0; j < 64; j++) { f[j] = __expf(f[j] - mx); s += f[j]; }
        float inv = 1.f / s;
        #pragma unroll
        for (int j = 0; j < 64; j++) f[j] *= inv;
        // store attn as fp16 (GEMM2 consumes it directly via cp.async)
        __half* dst = attnOut + (size_t)(row0 + r) * DDIM + col0 + hf * 64;
        #pragma unroll
        for (int j = 0; j < 8; j++) {
            __half2 p0 = __floats2half2_rn(f[8*j+0], f[8*j+1]);
            __half2 p1 = __floats2half2_rn(f[8*j+2], f[8*j+3]);
            __half2 p2 = __floats2half2_rn(f[8*j+4], f[8*j+5]);
            __half2 p3 = __floats2half2_rn(f[8*j+6], f[8*j+7]);
            *(uint4*)(dst + 8*j) =
                make_uint4(*(uint32_t*)&p0, *(uint32_t*)&p1, *(uint32_t*)&p2, *(uint32_t*)&p3);
        }
        __syncthreads();           // all Cs reads done; reuse as red[col][row]
        float* red = (float*)sm;
        #pragma unroll
        for (int j = 0; j < 64; j++) red[(hf * 64 + j) * 129 + r] = f[j];
        __syncthreads();
        if (tid < 128) {
            float s2 = 0.f;
            #pragma unroll 8
            for (int rr = 0; rr < 128; rr++) s2 += red[tid * 129 + rr];
            atomicAdd(&redOut[batch * DDIM + col0 + tid], s2);
        }
    }

    if (MODE == 2) {
        float bv[4][2];
        #pragma unroll
        for (int nt = 0; nt < 4; nt++)
            #pragma unroll
            for (int p = 0; p < 2; p++)
                bv[nt][p] = __ldg(&bias[col0 + wncol + nt * 8 + (lane & 3) * 2 + p]);
        float cs[4][2];
        #pragma unroll
        for (int nt = 0; nt < 4; nt++) { cs[nt][0] = 0.f; cs[nt][1] = 0.f; }
        #pragma unroll
        for (int mt = 0; mt < 4; mt++)
            #pragma unroll
            for (int nt = 0; nt < 4; nt++)
                #pragma unroll
                for (int rg = 0; rg < 4; rg++) {
                    float z = acc[mt][nt][rg] + bv[nt][rg & 1];
                    float g = 0.5f * z * (1.f + erff(z * 0.70710678118654752f));
                    cs[nt][rg & 1] += g;
                }
        float* red = (float*)sm;   // [128 cols][17 slots]
        const int slot = wm * 8 + (lane >> 2);
        __syncthreads();
        #pragma unroll
        for (int nt = 0; nt < 4; nt++)
            #pragma unroll
            for (int p = 0; p < 2; p++)
                red[(wncol + nt * 8 + (lane & 3) * 2 + p) * 17 + slot] = cs[nt][p];
        __syncthreads();
        if (tid < 128) {
            float s2 = 0.f;
            #pragma unroll
            for (int t = 0; t < 16; t++) s2 += red[tid * 17 + t];
            atomicAdd(&redOut[batch * DDIM + col0 + tid], s2);
        }
    }
}

// ---------------------------------------------------------------------------
// k_zero
// ---------------------------------------------------------------------------
__global__ void k_zero(float* __restrict__ G, float* __restrict__ A) {
    int i = blockIdx.x * blockDim.x + threadIdx.x;
    if (i < BATCH*DDIM) { G[i] = 0.f; A[i] = 0.f; }
}

// ---------------------------------------------------------------------------
// k_wl: W_l[d, h*R+r] = SCALE * sum_t wq[d, h*64+t] * kvl[r, h*64+t]
// ---------------------------------------------------------------------------
__global__ void k_wl(const float* __restrict__ wq, const float* __restrict__ kvl,
                     float* __restrict__ Wl) {
    __shared__ float kvs[64][65];
    __shared__ float wseg[64];
    int d = blockIdx.x, h = blockIdx.y;
    int tid = threadIdx.x;
    for (int t = 0; t < 64; t++)
        kvs[tid][t] = kvl[(size_t)tid*DDIM + h*HD + t];
    wseg[tid] = wq[(size_t)d*DDIM + h*HD + tid];
    __syncthreads();
    float s = 0.f;
    #pragma unroll
    for (int t = 0; t < 64; t++) s += wseg[t] * kvs[tid][t];
    Wl[(size_t)d*DDIM + h*RLAT + tid] = s * SCALE;
}

// ---------------------------------------------------------------------------
// k_p: P[j=(h*R+r), e] = sum_t kvl[r, h*64+t] * wo[h*64+t, e]
// ---------------------------------------------------------------------------
__global__ void k_p(const float* __restrict__ kvl, const float* __restrict__ wo,
                    float* __restrict__ P) {
    __shared__ float kv_s[HD];
    int j = blockIdx.x, h = j >> 6, r = j & 63;
    if (threadIdx.x < HD) kv_s[threadIdx.x] = kvl[(size_t)r*DDIM + h*HD + threadIdx.x];
    __syncthreads();
    float acc[4] = {0.f, 0.f, 0.f, 0.f};
    for (int t = 0; t < HD; t++) {
        float kvv = kv_s[t];
        const float* worow = wo + (size_t)(h*HD + t)*DDIM;
        #pragma unroll
        for (int ee = 0; ee < 4; ee++)
            acc[ee] += kvv * worow[threadIdx.x + 256*ee];
    }
    #pragma unroll
    for (int ee = 0; ee < 4; ee++)
        P[(size_t)j*DDIM + threadIdx.x + 256*ee] = acc[ee];
}

// ---------------------------------------------------------------------------
// gemm1k: fp32 SIMT GEMM for Q1 = P @ w1 (small: 1024^3)
// ---------------------------------------------------------------------------
__global__ void __launch_bounds__(256)
gemm1k(const float* __restrict__ A, const float* __restrict__ B, float* __restrict__ C) {
    extern __shared__ float sh[];
    float* As = sh;               // [16][128]
    float* Bs = sh + 16*128;
    const int tid = threadIdx.x;
    const int tx = tid & 15, ty = tid >> 4;
    const int row0 = blockIdx.y * 128, col0 = blockIdx.x * 128;
    float acc[8][8];
    #pragma unroll
    for (int i = 0; i < 8; i++)
        #pragma unroll
        for (int j = 0; j < 8; j++) acc[i][j] = 0.f;
    for (int kcb = 0; kcb < DDIM; kcb += 16) {
        #pragma unroll
        for (int i = 0; i < 2; i++) {
            int f = tid + i*256;
            int m = f >> 2, k4 = (f & 3) * 4;
            float4 v = *(const float4*)(A + (size_t)(row0+m)*DDIM + kcb + k4);
            As[(k4+0)*128 + m] = v.x; As[(k4+1)*128 + m] = v.y;
            As[(k4+2)*128 + m] = v.z; As[(k4+3)*128 + m] = v.w;
        }
        #pragma unroll
        for (int i = 0; i < 2; i++) {
            int f = tid + i*256;
            int k = f >> 5, n4 = (f & 31) * 4;
            *(float4*)(Bs + k*128 + n4) = *(const float4*)(B + (size_t)(kcb+k)*DDIM + col0 + n4);
        }
        __syncthreads();
        #pragma unroll
        for (int kk = 0; kk < 16; kk++) {
            float a[8], b[8];
            *(float4*)(a  ) = *(const float4*)(As + kk*128 + ty*8);
            *(float4*)(a+4) = *(const float4*)(As + kk*128 + ty*8 + 4);
            *(float4*)(b  ) = *(const float4*)(Bs + kk*128 + tx*8);
            *(float4*)(b+4) = *(const float4*)(Bs + kk*128 + tx*8 + 4);
            #pragma unroll
            for (int i = 0; i < 8; i++)
                #pragma unroll
                for (int j = 0; j < 8; j++)
                    acc[i][j] = fmaf(a[i], b[j], acc[i][j]);
        }
        __syncthreads();
    }
    #pragma unroll
    for (int i = 0; i < 8; i++) {
        *(float4*)(C + (size_t)(row0+ty*8+i)*DDIM + col0 + tx*8) =
            make_float4(acc[i][0], acc[i][1], acc[i][2], acc[i][3]);
        *(float4*)(C + (size_t)(row0+ty*8+i)*DDIM + col0 + tx*8 + 4) =
            make_float4(acc[i][4], acc[i][5], acc[i][6], acc[i][7]);
    }
}

// ---------------------------------------------------------------------------
// k_prepB: B[n][k] = split_fp16(W[k][n])  (transpose + hi/lo split)
// ---------------------------------------------------------------------------
__global__ void k_prepB(const float* __restrict__ W,
                        __half* __restrict__ Bh, __half* __restrict__ Bl) {
    __shared__ float t[32][33];
    int bx = blockIdx.x * 32, by = blockIdx.y * 32;
    int tx = threadIdx.x & 31, ty = threadIdx.x >> 5;  // 8 rows
    #pragma unroll
    for (int i = 0; i < 4; i++)
        t[ty + 8*i][tx] = W[(size_t)(by + ty + 8*i)*DDIM + bx + tx];
    __syncthreads();
    #pragma unroll
    for (int i = 0; i < 4; i++) {
        float v = t[tx][ty + 8*i];
        __half h = __float2half_rn(v);
        __half l = __float2half_rn(v - __half2float(h));
        Bh[(size_t)(bx + ty + 8*i)*DDIM + by + tx] = h;
        Bl[(size_t)(bx + ty + 8*i)*DDIM + by + tx] = l;
    }
}

// ---------------------------------------------------------------------------
// k_final: out[b,e] = b2[e] + (Gsum[b]/S) @ w2[:,e] + (Asum[b]/S) @ P[:,e]
// ---------------------------------------------------------------------------
__global__ void k_final(const float* __restrict__ w2, const float* __restrict__ b2,
                        const float* __restrict__ Gsum, const float* __restrict__ Asum,
                        const float* __restrict__ P, float* __restrict__ out) {
    int b = blockIdx.y;
    int e = blockIdx.x * 256 + threadIdx.x;
    __shared__ float gs[DDIM], as[DDIM];
    const float invS = 1.f / (float)SEQ;
    for (int i = threadIdx.x; i < DDIM; i += 256) {
        gs[i] = Gsum[b*DDIM + i] * invS;
        as[i] = Asum[b*DDIM + i] * invS;
    }
    __syncthreads();
    float a0 = 0.f, a1 = 0.f, a2 = 0.f, a3 = 0.f;
    for (int k = 0; k < DDIM; k += 4) {
        a0 = fmaf(gs[k  ], w2[(size_t)(k  )*DDIM + e], fmaf(as[k  ], P[(size_t)(k  )*DDIM + e], a0));
        a1 = fmaf(gs[k+1], w2[(size_t)(k+1)*DDIM + e], fmaf(as[k+1], P[(size_t)(k+1)*DDIM + e], a1));
        a2 = fmaf(gs[k+2], w2[(size_t)(k+2)*DDIM + e], fmaf(as[k+2], P[(size_t)(k+2)*DDIM + e], a2));
        a3 = fmaf(gs[k+3], w2[(size_t)(k+3)*DDIM + e], fmaf(as[k+3], P[(size_t)(k+3)*DDIM + e], a3));
    }
    out[b*DDIM + e] = b2[e] + ((a0 + a1) + (a2 + a3));
}

// ---------------------------------------------------------------------------
// Host launcher
// ---------------------------------------------------------------------------
extern "C" void kernel_launch(void* const* d_in, const int* in_sizes, int n_in,
                              void* d_out, int out_size) {
    const float* x   = (const float*)d_in[0];
    const float* wq  = (const float*)d_in[1];
    const float* kvl = (const float*)d_in[2];
    const float* wo  = (const float*)d_in[3];
    const float* w1  = (const float*)d_in[4];
    const float* b1  = (const float*)d_in[5];
    const float* w2  = (const float*)d_in[6];
    const float* b2  = (const float*)d_in[7];
    float* out = (float*)d_out;

    float *pWl, *pP, *pQ1, *pG, *pA;
    __half *pB1h, *pB1l, *pB2h, *pB2l, *pAttnH;
    cudaGetSymbolAddress((void**)&pWl,    g_Wl);
    cudaGetSymbolAddress((void**)&pP,     g_P);
    cudaGetSymbolAddress((void**)&pQ1,    g_Q1);
    cudaGetSymbolAddress((void**)&pG,     g_Gsum);
    cudaGetSymbolAddress((void**)&pA,     g_Asum);
    cudaGetSymbolAddress((void**)&pB1h,   g_B1h);
    cudaGetSymbolAddress((void**)&pB1l,   g_B1l);
    cudaGetSymbolAddress((void**)&pB2h,   g_B2h);
    cudaGetSymbolAddress((void**)&pB2l,   g_B2l);
    cudaGetSymbolAddress((void**)&pAttnH, g_attnH);

    cudaFuncSetAttribute(gemm1k, cudaFuncAttributeMaxDynamicSharedMemorySize, 65536);
    cudaFuncSetAttribute(wm_gemm<1,0>, cudaFuncAttributeMaxDynamicSharedMemorySize, WG_SMEM);
    cudaFuncSetAttribute(wm_gemm<2,1>, cudaFuncAttributeMaxDynamicSharedMemorySize, WG_SMEM);

    // 1. zero accumulators
    k_zero<<<(BATCH*DDIM + 255)/256, 256>>>(pG, pA);
    // 2. folded weights
    k_wl<<<dim3(DDIM, NHEAD), 64>>>(wq, kvl, pWl);
    k_p <<<DDIM, 256>>>(kvl, wo, pP);
    // 3. Q1 = P @ w1 (fp32 SIMT, small)
    gemm1k<<<dim3(8, 8), 256, 65536>>>(pP, w1, pQ1);
    // 4. split-fp16 transposed weights
    k_prepB<<<dim3(32, 32), 256>>>(pWl, pB1h, pB1l);
    k_prepB<<<dim3(32, 32), 256>>>(pQ1, pB2h, pB2l);
    // 5. attn = softmax(x @ Wl); Asum accumulated  [mma.sync fp16 x2]
    wm_gemm<1,0><<<dim3(8, NTOK/128), 256, WG_SMEM>>>(x, nullptr, pB1h, pB1l, nullptr, pAttnH, pA);
    // 6. Gsum += colsum(gelu(attn @ Q1 + b1))       [mma.sync fp16 x2, A=fp16]
    wm_gemm<2,1><<<dim3(8, NTOK/128), 256, WG_SMEM>>>(nullptr, pAttnH, pB2h, pB2l, b1, nullptr, pG);
    // 7. final tiny GEMMs + bias + residual mean
    k_final<<<dim3(4, BATCH), 256>>>(w2, b2, pG, pA, pP, out);
}

// round 7
// speedup vs baseline: 5.1438x; 1.7438x over previous
#include <cuda_runtime.h>
#include <cuda_fp16.h>
#include <cstdint>
#include <stdint.h>
#include <math.h>
#include <math_constants.h>

// Problem constants
#define BATCH  32
#define SEQ    4096
#define DDIM   1024
#define NTOK   (BATCH*SEQ)     // 131072
#define NHEAD  16
#define HD     64
#define RLAT   64
#define SCALE  0.125f          // R^-0.5

// ---------------------------------------------------------------------------
// Device scratch (static allocation; no cudaMalloc allowed)
// ---------------------------------------------------------------------------
__device__ float  g_P   [DDIM*DDIM];           // folded kv@wo (fp32, used by k_final)
__device__ __half g_B1  [DDIM*DDIM];           // Wl^T  fp16 (n-major, k contiguous)
__device__ __half g_B2  [DDIM*DDIM];           // Q1^T  fp16
__device__ __half g_attnH[(size_t)NTOK*DDIM];  // softmax(attn) fp16 (256 MB)
__device__ float  g_Gsum[BATCH*DDIM];
__device__ float  g_Asum[BATCH*DDIM];

// ---------------------------------------------------------------------------
// Portable PTX helpers (sm_80+ ISA — harness emits compute_103 PTX, so no
// tcgen05/TMA arch-specific instructions are available)
// ---------------------------------------------------------------------------
__device__ __forceinline__ uint32_t smem_u32(const void* p) {
    uint32_t a;
    asm("{ .reg .u64 t; cvta.to.shared.u64 t, %1; cvt.u32.u64 %0, t; }" : "=r"(a) : "l"(p));
    return a;
}
__device__ __forceinline__ void ldm_x4(uint32_t* r, uint32_t a) {
    asm volatile("ldmatrix.sync.aligned.m8n8.x4.shared.b16 {%0,%1,%2,%3}, [%4];"
        : "=r"(r[0]), "=r"(r[1]), "=r"(r[2]), "=r"(r[3]) : "r"(a));
}
__device__ __forceinline__ void mma16816(float* c, const uint32_t* a, const uint32_t* b) {
    asm volatile("mma.sync.aligned.m16n8k16.row.col.f32.f16.f16.f32 "
        "{%0,%1,%2,%3}, {%4,%5,%6,%7}, {%8,%9}, {%0,%1,%2,%3};"
        : "+f"(c[0]), "+f"(c[1]), "+f"(c[2]), "+f"(c[3])
        : "r"(a[0]), "r"(a[1]), "r"(a[2]), "r"(a[3]), "r"(b[0]), "r"(b[1]));
}
#define CP_ASYNC16(dst, src) \
    asm volatile("cp.async.cg.shared.global [%0], [%1], 16;" :: "r"(dst), "l"(src) : "memory")
#define CP_COMMIT() asm volatile("cp.async.commit_group;" ::: "memory")
#define CP_WAIT0()  asm volatile("cp.async.wait_group 0;" ::: "memory")

// 16B-unit XOR swizzle: row stride 64B (BK=32 fp16), unit u in 0..3
__device__ __forceinline__ int swz(int row, int u) {
    return row * 64 + ((u ^ ((row >> 1) & 3)) << 4);
}

// ---------------------------------------------------------------------------
// wm_gemm<MODE, AHALF>: C[128x128] = A @ B   [single-pass fp16 mma.sync]
//   A: fp32 (AHALF=0: LDG+convert+STS) or fp16 (AHALF=1: pure cp.async)
//   MODE 1: per-head softmax, store attn fp16, colsum -> redOut (Asum)
//   MODE 2: +bias, exact gelu, colsum -> redOut (Gsum); nothing stored
// 256 threads = 8 warps (2 M-halves x 4 N-quarters), warp tile 64x32, BK=32.
// Stage: A 8KB + B 8KB = 16KB, double buffered. 2 CTAs/SM.
// ---------------------------------------------------------------------------
#define NKC      32            // K chunks of 32
#define STG      16384         // bytes per stage
#define OFF_B    8192
#define SMEM_M1  67584         // epilogue Cs 128*132*4 (>= 2*STG)
#define SMEM_M2  32768         // 2*STG (red fits inside)

template<int MODE, int AHALF>
__global__ void __launch_bounds__(256, 2)
wm_gemm(const float* __restrict__ Af, const __half* __restrict__ Ah16,
        const __half* __restrict__ B,
        const float* __restrict__ bias,
        __half* __restrict__ attnOut, float* __restrict__ redOut)
{
    extern __shared__ char sm[];
    const uint32_t smb = smem_u32(sm);
    const int tid = threadIdx.x;
    const int lane = tid & 31, wid = tid >> 5;
    const int wm = wid & 1;                    // warp M half (0/1)
    const int wncol = (wid >> 1) * 32;         // warp N base col
    const int row0 = blockIdx.y * 128, col0 = blockIdx.x * 128;

    float acc[4][4][4];
    #pragma unroll
    for (int i = 0; i < 4; i++)
        #pragma unroll
        for (int j = 0; j < 4; j++)
            #pragma unroll
            for (int r = 0; r < 4; r++) acc[i][j][r] = 0.f;

    // per-thread staging unit coords (2 x 16B units per region)
    const int u0r = (tid + 0)   >> 2, u0u = (tid + 0)   & 3;
    const int u1r = (tid + 256) >> 2, u1u = (tid + 256) & 3;

    auto loadB = [&](int kc, int s) {
        uint32_t base = smb + s * STG;
        CP_ASYNC16(base + OFF_B + swz(u0r, u0u), B + (size_t)(col0 + u0r) * DDIM + kc * 32 + u0u * 8);
        CP_ASYNC16(base + OFF_B + swz(u1r, u1u), B + (size_t)(col0 + u1r) * DDIM + kc * 32 + u1u * 8);
    };
    auto loadA_async = [&](int kc, int s) {
        uint32_t base = smb + s * STG;
        CP_ASYNC16(base + swz(u0r, u0u), Ah16 + (size_t)(row0 + u0r) * DDIM + kc * 32 + u0u * 8);
        CP_ASYNC16(base + swz(u1r, u1u), Ah16 + (size_t)(row0 + u1r) * DDIM + kc * 32 + u1u * 8);
    };
    auto loadA_f32 = [&](int kc, float4* av) {
        const float* a0 = Af + (size_t)(row0 + u0r) * DDIM + kc * 32 + u0u * 8;
        const float* a1 = Af + (size_t)(row0 + u1r) * DDIM + kc * 32 + u1u * 8;
        av[0] = *(const float4*)(a0);
        av[1] = *(const float4*)(a0 + 4);
        av[2] = *(const float4*)(a1);
        av[3] = *(const float4*)(a1 + 4);
    };
    auto stsA = [&](const float4* av, int s) {
        char* base = sm + (size_t)s * STG;
        #pragma unroll
        for (int i = 0; i < 2; i++) {
            float4 v0 = av[2*i], v1 = av[2*i+1];
            __half2 h0 = __floats2half2_rn(v0.x, v0.y);
            __half2 h1 = __floats2half2_rn(v0.z, v0.w);
            __half2 h2 = __floats2half2_rn(v1.x, v1.y);
            __half2 h3 = __floats2half2_rn(v1.z, v1.w);
            int r = i ? u1r : u0r, u = i ? u1u : u0u;
            *(uint4*)(base + swz(r, u)) =
                make_uint4(*(uint32_t*)&h0, *(uint32_t*)&h1, *(uint32_t*)&h2, *(uint32_t*)&h3);
        }
    };

    // ---- prologue: chunk 0
    loadB(0, 0);
    if (AHALF) loadA_async(0, 0);
    CP_COMMIT();
    if (!AHALF) { float4 av[4]; loadA_f32(0, av); stsA(av, 0); }
    CP_WAIT0(); __syncthreads();

    // ---- main loop
    for (int kc = 0; kc < NKC; kc++) {
        const int cur = kc & 1;
        float4 av[4];
        if (kc < NKC - 1) {
            loadB(kc + 1, cur ^ 1);
            if (AHALF) loadA_async(kc + 1, cur ^ 1);
            CP_COMMIT();
            if (!AHALF) loadA_f32(kc + 1, av);
        }

        const uint32_t sA = smb + cur * STG;
        #pragma unroll
        for (int kk = 0; kk < 2; kk++) {
            uint32_t ah[4][4], bh[4][2];
            #pragma unroll
            for (int mt = 0; mt < 4; mt++) {
                int arow = wm * 64 + mt * 16 + (lane & 7) + ((lane >> 3) & 1) * 8;
                int au   = kk * 2 + (lane >> 4);
                ldm_x4(ah[mt], sA + swz(arow, au));
            }
            #pragma unroll
            for (int nt2 = 0; nt2 < 2; nt2++) {
                int brow = wncol + nt2 * 16 + ((lane >> 4) << 3) + (lane & 7);
                int bu   = kk * 2 + ((lane >> 3) & 1);
                uint32_t r4[4];
                ldm_x4(r4, sA + OFF_B + swz(brow, bu));
                bh[2*nt2][0] = r4[0]; bh[2*nt2][1] = r4[1];
                bh[2*nt2+1][0] = r4[2]; bh[2*nt2+1][1] = r4[3];
            }
            #pragma unroll
            for (int mt = 0; mt < 4; mt++)
                #pragma unroll
                for (int nt = 0; nt < 4; nt++)
                    mma16816(acc[mt][nt], ah[mt], bh[nt]);
        }
        if (!AHALF && kc < NKC - 1) stsA(av, cur ^ 1);
        CP_WAIT0(); __syncthreads();
    }

    const int batch = row0 >> 12;   // SEQ = 4096

    if (MODE == 1) {
        // stage C tile to smem (stride 132 floats: float4-aligned rows)
        float* Cs = (float*)sm;
        #pragma unroll
        for (int mt = 0; mt < 4; mt++)
            #pragma unroll
            for (int nt = 0; nt < 4; nt++) {
                int row = wm * 64 + mt * 16 + (lane >> 2);
                int col = wncol + nt * 8 + (lane & 3) * 2;
                *(float2*)&Cs[row * 132 + col]       = make_float2(acc[mt][nt][0], acc[mt][nt][1]);
                *(float2*)&Cs[(row + 8) * 132 + col] = make_float2(acc[mt][nt][2], acc[mt][nt][3]);
            }
        __syncthreads();
        // per-thread softmax over one 64-latent head segment
        const int r = tid >> 1, hf = tid & 1;
        float f[64];
        #pragma unroll
        for (int j = 0; j < 16; j++)
            *(float4*)&f[j * 4] = *(const float4*)&Cs[r * 132 + hf * 64 + j * 4];
        float mx = -CUDART_INF_F;
        #pragma unroll
        for (int j = 0; j < 64; j++) mx = fmaxf(mx, f[j]);
        float s = 0.f;
        #pragma unroll
        for (int j = 0; j < 64; j++) { f[j] = __expf(f[j] - mx); s += f[j]; }
        float inv = 1.f / s;
        #pragma unroll
        for (int j = 0; j < 64; j++) f[j] *= inv;
        // store attn as fp16 (GEMM2 consumes directly via cp.async)
        __half* dst = attnOut + (size_t)(row0 + r) * DDIM + col0 + hf * 64;
        #pragma unroll
        for (int j = 0; j < 8; j++) {
            __half2 p0 = __floats2half2_rn(f[8*j+0], f[8*j+1]);
            __half2 p1 = __floats2half2_rn(f[8*j+2], f[8*j+3]);
            __half2 p2 = __floats2half2_rn(f[8*j+4], f[8*j+5]);
            __half2 p3 = __floats2half2_rn(f[8*j+6], f[8*j+7]);
            *(uint4*)(dst + 8*j) =
                make_uint4(*(uint32_t*)&p0, *(uint32_t*)&p1, *(uint32_t*)&p2, *(uint32_t*)&p3);
        }
        __syncthreads();           // all Cs reads done; reuse as red[col][row]
        float* red = (float*)sm;
        #pragma unroll
        for (int j = 0; j < 64; j++) red[(hf * 64 + j) * 129 + r] = f[j];
        __syncthreads();
        if (tid < 128) {
            float s2 = 0.f;
            #pragma unroll 8
            for (int rr = 0; rr < 128; rr++) s2 += red[tid * 129 + rr];
            atomicAdd(&redOut[batch * DDIM + col0 + tid], s2);
        }
    }

    if (MODE == 2) {
        float bv[4][2];
        #pragma unroll
        for (int nt = 0; nt < 4; nt++)
            #pragma unroll
            for (int p = 0; p < 2; p++)
                bv[nt][p] = __ldg(&bias[col0 + wncol + nt * 8 + (lane & 3) * 2 + p]);
        float cs[4][2];
        #pragma unroll
        for (int nt = 0; nt < 4; nt++) { cs[nt][0] = 0.f; cs[nt][1] = 0.f; }
        #pragma unroll
        for (int mt = 0; mt < 4; mt++)
            #pragma unroll
            for (int nt = 0; nt < 4; nt++)
                #pragma unroll
                for (int rg = 0; rg < 4; rg++) {
                    float z = acc[mt][nt][rg] + bv[nt][rg & 1];
                    float g = 0.5f * z * (1.f + erff(z * 0.70710678118654752f));
                    cs[nt][rg & 1] += g;
                }
        float* red = (float*)sm;   // [128 cols][17 slots]
        const int slot = wm * 8 + (lane >> 2);
        __syncthreads();
        #pragma unroll
        for (int nt = 0; nt < 4; nt++)
            #pragma unroll
            for (int p = 0; p < 2; p++)
                red[(wncol + nt * 8 + (lane & 3) * 2 + p) * 17 + slot] = cs[nt][p];
        __syncthreads();
        if (tid < 128) {
            float s2 = 0.f;
            #pragma unroll
            for (int t = 0; t < 16; t++) s2 += red[tid * 17 + t];
            atomicAdd(&redOut[batch * DDIM + col0 + tid], s2);
        }
    }
}

// ---------------------------------------------------------------------------
// k_zero
// ---------------------------------------------------------------------------
__global__ void k_zero(float* __restrict__ G, float* __restrict__ A) {
    int i = blockIdx.x * blockDim.x + threadIdx.x;
    if (i < BATCH*DDIM) { G[i] = 0.f; A[i] = 0.f; }
}

// ---------------------------------------------------------------------------
// k_wl: directly emits B1[n=(h*R+r)][k=d] = fp16(SCALE * wq[d,h*64+:]·kvl[r,h*64+:])
// grid (1024 d, 16 h), 64 threads (one r each)
// ---------------------------------------------------------------------------
__global__ void k_wl(const float* __restrict__ wq, const float* __restrict__ kvl,
                     __half* __restrict__ B1) {
    __shared__ float kvs[64][65];
    __shared__ float wseg[64];
    int d = blockIdx.x, h = blockIdx.y;
    int tid = threadIdx.x;
    for (int t = 0; t < 64; t++)
        kvs[tid][t] = kvl[(size_t)tid*DDIM + h*HD + t];
    wseg[tid] = wq[(size_t)d*DDIM + h*HD + tid];
    __syncthreads();
    float s = 0.f;
    #pragma unroll
    for (int t = 0; t < 64; t++) s += wseg[t] * kvs[tid][t];
    B1[(size_t)(h*RLAT + tid)*DDIM + d] = __float2half_rn(s * SCALE);
}

// ---------------------------------------------------------------------------
// k_p: P[j=(h*R+r), e] = sum_t kvl[r, h*64+t] * wo[h*64+t, e]   (fp32)
// ---------------------------------------------------------------------------
__global__ void k_p(const float* __restrict__ kvl, const float* __restrict__ wo,
                    float* __restrict__ P) {
    __shared__ float kv_s[HD];
    int j = blockIdx.x, h = j >> 6, r = j & 63;
    if (threadIdx.x < HD) kv_s[threadIdx.x] = kvl[(size_t)r*DDIM + h*HD + threadIdx.x];
    __syncthreads();
    float acc[4] = {0.f, 0.f, 0.f, 0.f};
    for (int t = 0; t < HD; t++) {
        float kvv = kv_s[t];
        const float* worow = wo + (size_t)(h*HD + t)*DDIM;
        #pragma unroll
        for (int ee = 0; ee < 4; ee++)
            acc[ee] += kvv * worow[threadIdx.x + 256*ee];
    }
    #pragma unroll
    for (int ee = 0; ee < 4; ee++)
        P[(size_t)j*DDIM + threadIdx.x + 256*ee] = acc[ee];
}

// ---------------------------------------------------------------------------
// gemm1k: Q1 = P @ w1 (fp32 SIMT), emits B2[n][k] = fp16(Q1[k][n]) directly
// ---------------------------------------------------------------------------
__global__ void __launch_bounds__(256)
gemm1k(const float* __restrict__ A, const float* __restrict__ B, __half* __restrict__ B2) {
    extern __shared__ float sh[];
    float* As = sh;               // [16][128]
    float* Bs = sh + 16*128;
    const int tid = threadIdx.x;
    const int tx = tid & 15, ty = tid >> 4;
    const int row0 = blockIdx.y * 128, col0 = blockIdx.x * 128;
    float acc[8][8];
    #pragma unroll
    for (int i = 0; i < 8; i++)
        #pragma unroll
        for (int j = 0; j < 8; j++) acc[i][j] = 0.f;
    for (int kcb = 0; kcb < DDIM; kcb += 16) {
        #pragma unroll
        for (int i = 0; i < 2; i++) {
            int f = tid + i*256;
            int m = f >> 2, k4 = (f & 3) * 4;
            float4 v = *(const float4*)(A + (size_t)(row0+m)*DDIM + kcb + k4);
            As[(k4+0)*128 + m] = v.x; As[(k4+1)*128 + m] = v.y;
            As[(k4+2)*128 + m] = v.z; As[(k4+3)*128 + m] = v.w;
        }
        #pragma unroll
        for (int i = 0; i < 2; i++) {
            int f = tid + i*256;
            int k = f >> 5, n4 = (f & 31) * 4;
            *(float4*)(Bs + k*128 + n4) = *(const float4*)(B + (size_t)(kcb+k)*DDIM + col0 + n4);
        }
        __syncthreads();
        #pragma unroll
        for (int kk = 0; kk < 16; kk++) {
            float a[8], b[8];
            *(float4*)(a  ) = *(const float4*)(As + kk*128 + ty*8);
            *(float4*)(a+4) = *(const float4*)(As + kk*128 + ty*8 + 4);
            *(float4*)(b  ) = *(const float4*)(Bs + kk*128 + tx*8);
            *(float4*)(b+4) = *(const float4*)(Bs + kk*128 + tx*8 + 4);
            #pragma unroll
            for (int i = 0; i < 8; i++)
                #pragma unroll
                for (int j = 0; j < 8; j++)
                    acc[i][j] = fmaf(a[i], b[j], acc[i][j]);
        }
        __syncthreads();
    }
    // transposed fp16 store: B2[(col0+tx*8+j)*DDIM + row0+ty*8+i]
    #pragma unroll
    for (int j = 0; j < 8; j++) {
        __half* dst = B2 + (size_t)(col0 + tx*8 + j)*DDIM + row0 + ty*8;
        __half2 q0 = __floats2half2_rn(acc[0][j], acc[1][j]);
        __half2 q1 = __floats2half2_rn(acc[2][j], acc[3][j]);
        __half2 q2 = __floats2half2_rn(acc[4][j], acc[5][j]);
        __half2 q3 = __floats2half2_rn(acc[6][j], acc[7][j]);
        *(uint4*)dst = make_uint4(*(uint32_t*)&q0, *(uint32_t*)&q1,
                                  *(uint32_t*)&q2, *(uint32_t*)&q3);
    }
}

// ---------------------------------------------------------------------------
// k_final: out[b,e] = b2[e] + (Gsum[b]/S) @ w2[:,e] + (Asum[b]/S) @ P[:,e]
// ---------------------------------------------------------------------------
__global__ void k_final(const float* __restrict__ w2, const float* __restrict__ b2,
                        const float* __restrict__ Gsum, const float* __restrict__ Asum,
                        const float* __restrict__ P, float* __restrict__ out) {
    int b = blockIdx.y;
    int e = blockIdx.x * 256 + threadIdx.x;
    __shared__ float gs[DDIM], as[DDIM];
    const float invS = 1.f / (float)SEQ;
    for (int i = threadIdx.x; i < DDIM; i += 256) {
        gs[i] = Gsum[b*DDIM + i] * invS;
        as[i] = Asum[b*DDIM + i] * invS;
    }
    __syncthreads();
    float a0 = 0.f, a1 = 0.f, a2 = 0.f, a3 = 0.f;
    for (int k = 0; k < DDIM; k += 4) {
        a0 = fmaf(gs[k  ], w2[(size_t)(k  )*DDIM + e], fmaf(as[k  ], P[(size_t)(k  )*DDIM + e], a0));
        a1 = fmaf(gs[k+1], w2[(size_t)(k+1)*DDIM + e], fmaf(as[k+1], P[(size_t)(k+1)*DDIM + e], a1));
        a2 = fmaf(gs[k+2], w2[(size_t)(k+2)*DDIM + e], fmaf(as[k+2], P[(size_t)(k+2)*DDIM + e], a2));
        a3 = fmaf(gs[k+3], w2[(size_t)(k+3)*DDIM + e], fmaf(as[k+3], P[(size_t)(k+3)*DDIM + e], a3));
    }
    out[b*DDIM + e] = b2[e] + ((a0 + a1) + (a2 + a3));
}

// ---------------------------------------------------------------------------
// Host launcher
// ---------------------------------------------------------------------------
extern "C" void kernel_launch(void* const* d_in, const int* in_sizes, int n_in,
                              void* d_out, int out_size) {
    const float* x   = (const float*)d_in[0];
    const float* wq  = (const float*)d_in[1];
    const float* kvl = (const float*)d_in[2];
    const float* wo  = (const float*)d_in[3];
    const float* w1  = (const float*)d_in[4];
    const float* b1  = (const float*)d_in[5];
    const float* w2  = (const float*)d_in[6];
    const float* b2  = (const float*)d_in[7];
    float* out = (float*)d_out;

    float *pP, *pG, *pA;
    __half *pB1, *pB2, *pAttnH;
    cudaGetSymbolAddress((void**)&pP,     g_P);
    cudaGetSymbolAddress((void**)&pG,     g_Gsum);
    cudaGetSymbolAddress((void**)&pA,     g_Asum);
    cudaGetSymbolAddress((void**)&pB1,    g_B1);
    cudaGetSymbolAddress((void**)&pB2,    g_B2);
    cudaGetSymbolAddress((void**)&pAttnH, g_attnH);

    cudaFuncSetAttribute(gemm1k, cudaFuncAttributeMaxDynamicSharedMemorySize, 65536);
    cudaFuncSetAttribute(wm_gemm<1,0>, cudaFuncAttributeMaxDynamicSharedMemorySize, SMEM_M1);
    cudaFuncSetAttribute(wm_gemm<2,1>, cudaFuncAttributeMaxDynamicSharedMemorySize, SMEM_M2);

    // 1. zero accumulators
    k_zero<<<(BATCH*DDIM + 255)/256, 256>>>(pG, pA);
    // 2. folded weights (B1 emitted directly as fp16 transposed)
    k_wl<<<dim3(DDIM, NHEAD), 64>>>(wq, kvl, pB1);
    k_p <<<DDIM, 256>>>(kvl, wo, pP);
    // 3. Q1 = P @ w1, emitted directly as fp16 transposed B2
    gemm1k<<<dim3(8, 8), 256, 65536>>>(pP, w1, pB2);
    // 4. attn = softmax(x @ Wl); Asum accumulated  [mma.sync fp16 x1]
    wm_gemm<1,0><<<dim3(8, NTOK/128), 256, SMEM_M1>>>(x, nullptr, pB1, nullptr, pAttnH, pA);
    // 5. Gsum += colsum(gelu(attn @ Q1 + b1))       [mma.sync fp16 x1, A=fp16]
    wm_gemm<2,1><<<dim3(8, NTOK/128), 256, SMEM_M2>>>(nullptr, pAttnH, pB2, b1, nullptr, pG);
    // 6. final tiny GEMMs + bias + residual mean
    k_final<<<dim3(4, BATCH), 256>>>(w2, b2, pG, pA, pP, out);
}

// round 9
// speedup vs baseline: 5.9178x; 1.1505x over previous
#include <cuda_runtime.h>
#include <cuda_fp16.h>
#include <cstdint>
#include <stdint.h>
#include <math.h>
#include <math_constants.h>

// Problem constants
#define BATCH  32
#define SEQ    4096
#define DDIM   1024
#define NTOK   (BATCH*SEQ)     // 131072
#define NHEAD  16
#define HD     64
#define RLAT   64
#define SCALE  0.125f          // R^-0.5

// ---------------------------------------------------------------------------
// Device scratch (static allocation; no cudaMalloc allowed)
// ---------------------------------------------------------------------------
__device__ float  g_P   [DDIM*DDIM];           // folded kv@wo (fp32, used by k_final)
__device__ __half g_W1T [DDIM*DDIM];           // w1^T fp16 (n-major, k contiguous)
__device__ __half g_B1  [DDIM*DDIM];           // Wl^T  fp16 (n-major, k contiguous)
__device__ __half g_B2  [DDIM*DDIM];           // Q1^T  fp16
__device__ __half g_attnH[(size_t)NTOK*DDIM];  // softmax(attn) fp16 (256 MB)
__device__ float  g_Gsum[BATCH*DDIM];
__device__ float  g_Asum[BATCH*DDIM];

// ---------------------------------------------------------------------------
// Portable PTX helpers (sm_80+ ISA — harness emits compute_103 PTX, so no
// tcgen05/TMA arch-specific instructions are available)
// ---------------------------------------------------------------------------
__device__ __forceinline__ uint32_t smem_u32(const void* p) {
    uint32_t a;
    asm("{ .reg .u64 t; cvta.to.shared.u64 t, %1; cvt.u32.u64 %0, t; }" : "=r"(a) : "l"(p));
    return a;
}
__device__ __forceinline__ void ldm_x4(uint32_t* r, uint32_t a) {
    asm volatile("ldmatrix.sync.aligned.m8n8.x4.shared.b16 {%0,%1,%2,%3}, [%4];"
        : "=r"(r[0]), "=r"(r[1]), "=r"(r[2]), "=r"(r[3]) : "r"(a));
}
__device__ __forceinline__ void mma16816(float* c, const uint32_t* a, const uint32_t* b) {
    asm volatile("mma.sync.aligned.m16n8k16.row.col.f32.f16.f16.f32 "
        "{%0,%1,%2,%3}, {%4,%5,%6,%7}, {%8,%9}, {%0,%1,%2,%3};"
        : "+f"(c[0]), "+f"(c[1]), "+f"(c[2]), "+f"(c[3])
        : "r"(a[0]), "r"(a[1]), "r"(a[2]), "r"(a[3]), "r"(b[0]), "r"(b[1]));
}
#define CP_ASYNC16(dst, src) \
    asm volatile("cp.async.cg.shared.global [%0], [%1], 16;" :: "r"(dst), "l"(src) : "memory")
#define CP_COMMIT() asm volatile("cp.async.commit_group;" ::: "memory")
#define CP_WAIT0()  asm volatile("cp.async.wait_group 0;" ::: "memory")

// 16B-unit XOR swizzle: row stride 64B (BK=32 fp16), unit u in 0..3
__device__ __forceinline__ int swz(int row, int u) {
    return row * 64 + ((u ^ ((row >> 1) & 3)) << 4);
}

// ---------------------------------------------------------------------------
// wm_gemm<MODE, AHALF>: C[128x128] = A @ B   [single-pass fp16 mma.sync]
//   A: fp32 (AHALF=0: LDG+convert+STS) or fp16 (AHALF=1: pure cp.async)
//   MODE 0: store C^T as fp16 to outH  (used for B2 = Q1^T = (P@w1)^T)
//   MODE 1: per-head softmax, store attn fp16, colsum -> redOut (Asum)
//   MODE 2: +bias, exact gelu, colsum -> redOut (Gsum); nothing stored
// 256 threads = 8 warps (2 M-halves x 4 N-quarters), warp tile 64x32, BK=32.
// Stage: A 8KB + B 8KB = 16KB, double buffered. 2 CTAs/SM.
// ---------------------------------------------------------------------------
#define NKC      32            // K chunks of 32
#define STG      16384         // bytes per stage
#define OFF_B    8192
#define SMEM_M1  67584         // epilogue Cs 128*132*4 (>= 2*STG)
#define SMEM_M2  32768         // 2*STG (red fits inside)

template<int MODE, int AHALF>
__global__ void __launch_bounds__(256, 2)
wm_gemm(const float* __restrict__ Af, const __half* __restrict__ Ah16,
        const __half* __restrict__ B,
        const float* __restrict__ bias,
        __half* __restrict__ outH, float* __restrict__ redOut)
{
    extern __shared__ char sm[];
    const uint32_t smb = smem_u32(sm);
    const int tid = threadIdx.x;
    const int lane = tid & 31, wid = tid >> 5;
    const int wm = wid & 1;                    // warp M half (0/1)
    const int wncol = (wid >> 1) * 32;         // warp N base col
    const int row0 = blockIdx.y * 128, col0 = blockIdx.x * 128;

    float acc[4][4][4];
    #pragma unroll
    for (int i = 0; i < 4; i++)
        #pragma unroll
        for (int j = 0; j < 4; j++)
            #pragma unroll
            for (int r = 0; r < 4; r++) acc[i][j][r] = 0.f;

    // per-thread staging unit coords (2 x 16B units per region)
    const int u0r = (tid + 0)   >> 2, u0u = (tid + 0)   & 3;
    const int u1r = (tid + 256) >> 2, u1u = (tid + 256) & 3;

    auto loadB = [&](int kc, int s) {
        uint32_t base = smb + s * STG;
        CP_ASYNC16(base + OFF_B + swz(u0r, u0u), B + (size_t)(col0 + u0r) * DDIM + kc * 32 + u0u * 8);
        CP_ASYNC16(base + OFF_B + swz(u1r, u1u), B + (size_t)(col0 + u1r) * DDIM + kc * 32 + u1u * 8);
    };
    auto loadA_async = [&](int kc, int s) {
        uint32_t base = smb + s * STG;
        CP_ASYNC16(base + swz(u0r, u0u), Ah16 + (size_t)(row0 + u0r) * DDIM + kc * 32 + u0u * 8);
        CP_ASYNC16(base + swz(u1r, u1u), Ah16 + (size_t)(row0 + u1r) * DDIM + kc * 32 + u1u * 8);
    };
    auto loadA_f32 = [&](int kc, float4* av) {
        const float* a0 = Af + (size_t)(row0 + u0r) * DDIM + kc * 32 + u0u * 8;
        const float* a1 = Af + (size_t)(row0 + u1r) * DDIM + kc * 32 + u1u * 8;
        av[0] = *(const float4*)(a0);
        av[1] = *(const float4*)(a0 + 4);
        av[2] = *(const float4*)(a1);
        av[3] = *(const float4*)(a1 + 4);
    };
    auto stsA = [&](const float4* av, int s) {
        char* base = sm + (size_t)s * STG;
        #pragma unroll
        for (int i = 0; i < 2; i++) {
            float4 v0 = av[2*i], v1 = av[2*i+1];
            __half2 h0 = __floats2half2_rn(v0.x, v0.y);
            __half2 h1 = __floats2half2_rn(v0.z, v0.w);
            __half2 h2 = __floats2half2_rn(v1.x, v1.y);
            __half2 h3 = __floats2half2_rn(v1.z, v1.w);
            int r = i ? u1r : u0r, u = i ? u1u : u0u;
            *(uint4*)(base + swz(r, u)) =
                make_uint4(*(uint32_t*)&h0, *(uint32_t*)&h1, *(uint32_t*)&h2, *(uint32_t*)&h3);
        }
    };

    // ---- prologue: chunk 0
    loadB(0, 0);
    if (AHALF) loadA_async(0, 0);
    CP_COMMIT();
    if (!AHALF) { float4 av[4]; loadA_f32(0, av); stsA(av, 0); }
    CP_WAIT0(); __syncthreads();

    // ---- main loop
    for (int kc = 0; kc < NKC; kc++) {
        const int cur = kc & 1;
        float4 av[4];
        if (kc < NKC - 1) {
            loadB(kc + 1, cur ^ 1);
            if (AHALF) loadA_async(kc + 1, cur ^ 1);
            CP_COMMIT();
            if (!AHALF) loadA_f32(kc + 1, av);
        }

        const uint32_t sA = smb + cur * STG;
        #pragma unroll
        for (int kk = 0; kk < 2; kk++) {
            uint32_t ah[4][4], bh[4][2];
            #pragma unroll
            for (int mt = 0; mt < 4; mt++) {
                int arow = wm * 64 + mt * 16 + (lane & 7) + ((lane >> 3) & 1) * 8;
                int au   = kk * 2 + (lane >> 4);
                ldm_x4(ah[mt], sA + swz(arow, au));
            }
            #pragma unroll
            for (int nt2 = 0; nt2 < 2; nt2++) {
                int brow = wncol + nt2 * 16 + ((lane >> 4) << 3) + (lane & 7);
                int bu   = kk * 2 + ((lane >> 3) & 1);
                uint32_t r4[4];
                ldm_x4(r4, sA + OFF_B + swz(brow, bu));
                bh[2*nt2][0] = r4[0]; bh[2*nt2][1] = r4[1];
                bh[2*nt2+1][0] = r4[2]; bh[2*nt2+1][1] = r4[3];
            }
            #pragma unroll
            for (int mt = 0; mt < 4; mt++)
                #pragma unroll
                for (int nt = 0; nt < 4; nt++)
                    mma16816(acc[mt][nt], ah[mt], bh[nt]);
        }
        if (!AHALF && kc < NKC - 1) stsA(av, cur ^ 1);
        CP_WAIT0(); __syncthreads();
    }

    const int batch = row0 >> 12;   // SEQ = 4096

    if (MODE == 0 || MODE == 1) {
        // stage C tile to smem (stride 132 floats: float4-aligned rows)
        float* Cs = (float*)sm;
        #pragma unroll
        for (int mt = 0; mt < 4; mt++)
            #pragma unroll
            for (int nt = 0; nt < 4; nt++) {
                int row = wm * 64 + mt * 16 + (lane >> 2);
                int col = wncol + nt * 8 + (lane & 3) * 2;
                *(float2*)&Cs[row * 132 + col]       = make_float2(acc[mt][nt][0], acc[mt][nt][1]);
                *(float2*)&Cs[(row + 8) * 132 + col] = make_float2(acc[mt][nt][2], acc[mt][nt][3]);
            }
        __syncthreads();

        if (MODE == 0) {
            // transposed fp16 store: outH[(col0+n)*DDIM + row0+m]
            const int n = tid >> 1, half = tid & 1;
            __half* dst = outH + (size_t)(col0 + n) * DDIM + row0 + half * 64;
            #pragma unroll
            for (int j = 0; j < 32; j++) {
                __half2 p = __floats2half2_rn(Cs[(half*64 + 2*j    ) * 132 + n],
                                              Cs[(half*64 + 2*j + 1) * 132 + n]);
                ((uint32_t*)dst)[j] = *(uint32_t*)&p;
            }
        }

        if (MODE == 1) {
            // per-thread softmax over one 64-latent head segment
            const int r = tid >> 1, hf = tid & 1;
            float f[64];
            #pragma unroll
            for (int j = 0; j < 16; j++)
                *(float4*)&f[j * 4] = *(const float4*)&Cs[r * 132 + hf * 64 + j * 4];
            float mx = -CUDART_INF_F;
            #pragma unroll
            for (int j = 0; j < 64; j++) mx = fmaxf(mx, f[j]);
            float s = 0.f;
            #pragma unroll
            for (int j = 0; j < 64; j++) { f[j] = __expf(f[j] - mx); s += f[j]; }
            float inv = 1.f / s;
            #pragma unroll
            for (int j = 0; j < 64; j++) f[j] *= inv;
            // store attn as fp16 (GEMM2 consumes directly via cp.async)
            __half* dst = outH + (size_t)(row0 + r) * DDIM + col0 + hf * 64;
            #pragma unroll
            for (int j = 0; j < 8; j++) {
                __half2 p0 = __floats2half2_rn(f[8*j+0], f[8*j+1]);
                __half2 p1 = __floats2half2_rn(f[8*j+2], f[8*j+3]);
                __half2 p2 = __floats2half2_rn(f[8*j+4], f[8*j+5]);
                __half2 p3 = __floats2half2_rn(f[8*j+6], f[8*j+7]);
                *(uint4*)(dst + 8*j) =
                    make_uint4(*(uint32_t*)&p0, *(uint32_t*)&p1, *(uint32_t*)&p2, *(uint32_t*)&p3);
            }
            __syncthreads();           // all Cs reads done; reuse as red[col][row]
            float* red = (float*)sm;
            #pragma unroll
            for (int j = 0; j < 64; j++) red[(hf * 64 + j) * 129 + r] = f[j];
            __syncthreads();
            if (tid < 128) {
                float s2 = 0.f;
                #pragma unroll 8
                for (int rr = 0; rr < 128; rr++) s2 += red[tid * 129 + rr];
                atomicAdd(&redOut[batch * DDIM + col0 + tid], s2);
            }
        }
    }

    if (MODE == 2) {
        float bv[4][2];
        #pragma unroll
        for (int nt = 0; nt < 4; nt++)
            #pragma unroll
            for (int p = 0; p < 2; p++)
                bv[nt][p] = __ldg(&bias[col0 + wncol + nt * 8 + (lane & 3) * 2 + p]);
        float cs[4][2];
        #pragma unroll
        for (int nt = 0; nt < 4; nt++) { cs[nt][0] = 0.f; cs[nt][1] = 0.f; }
        #pragma unroll
        for (int mt = 0; mt < 4; mt++)
            #pragma unroll
            for (int nt = 0; nt < 4; nt++)
                #pragma unroll
                for (int rg = 0; rg < 4; rg++) {
                    float z = acc[mt][nt][rg] + bv[nt][rg & 1];
                    float g = 0.5f * z * (1.f + erff(z * 0.70710678118654752f));
                    cs[nt][rg & 1] += g;
                }
        float* red = (float*)sm;   // [128 cols][17 slots]
        const int slot = wm * 8 + (lane >> 2);
        __syncthreads();
        #pragma unroll
        for (int nt = 0; nt < 4; nt++)
            #pragma unroll
            for (int p = 0; p < 2; p++)
                red[(wncol + nt * 8 + (lane & 3) * 2 + p) * 17 + slot] = cs[nt][p];
        __syncthreads();
        if (tid < 128) {
            float s2 = 0.f;
            #pragma unroll
            for (int t = 0; t < 16; t++) s2 += red[tid * 17 + t];
            atomicAdd(&redOut[batch * DDIM + col0 + tid], s2);
        }
    }
}

// ---------------------------------------------------------------------------
// k_zero
// ---------------------------------------------------------------------------
__global__ void k_zero(float* __restrict__ G, float* __restrict__ A) {
    int i = blockIdx.x * blockDim.x + threadIdx.x;
    if (i < BATCH*DDIM) { G[i] = 0.f; A[i] = 0.f; }
}

// ---------------------------------------------------------------------------
// k_wl: B1[(h*64+r)][d] = fp16(SCALE * wq[d,h*64+:]·kvl[r,h*64+:])
// grid (8 d-chunks, 16 h), 256 threads. kv segment loaded once per block.
// ---------------------------------------------------------------------------
__global__ void __launch_bounds__(256)
k_wl(const float* __restrict__ wq, const float* __restrict__ kvl,
     __half* __restrict__ B1) {
    __shared__ float kvs[64][65];
    __shared__ float wseg[4][64];
    __shared__ __half wl[64][128];
    const int h = blockIdx.y, dbase = blockIdx.x * 128;
    const int tid = threadIdx.x;
    #pragma unroll
    for (int i = 0; i < 16; i++) {
        int idx = tid + i * 256;
        int r = idx >> 6, t = idx & 63;
        kvs[r][t] = kvl[(size_t)r * DDIM + h * HD + t];
    }
    __syncthreads();
    const int r = tid & 63, dsel = tid >> 6;
    for (int it = 0; it < 32; it++) {
        wseg[dsel][r] = wq[(size_t)(dbase + it * 4 + dsel) * DDIM + h * HD + r];
        __syncthreads();
        float s = 0.f;
        #pragma unroll
        for (int t = 0; t < 64; t++) s += wseg[dsel][t] * kvs[r][t];
        wl[r][it * 4 + dsel] = __float2half_rn(s * SCALE);
        __syncthreads();
    }
    // coalesced write: B1 rows (h*64+r), cols dbase..dbase+128
    #pragma unroll
    for (int i = 0; i < 16; i++) {
        int idx = tid + i * 256;       // 4096 uint32 = 8192 halves
        int rr = idx >> 6, c2 = idx & 63;
        *(uint32_t*)&B1[(size_t)(h * HD + rr) * DDIM + dbase + c2 * 2] =
            *(uint32_t*)&wl[rr][c2 * 2];
    }
}

// ---------------------------------------------------------------------------
// k_p: P[(h*64+r)][e] = sum_t kvl[r, h*64+t] * wo[h*64+t, e]   (fp32)
// grid (8 e-chunks, 16 h), 256 threads. wo streamed once total (4MB).
// ---------------------------------------------------------------------------
__global__ void __launch_bounds__(256)
k_p(const float* __restrict__ kvl, const float* __restrict__ wo,
    float* __restrict__ P) {
    __shared__ float kvs[64][65];
    __shared__ float woS[2][128];
    const int h = blockIdx.y, ebase = blockIdx.x * 128;
    const int tid = threadIdx.x;
    #pragma unroll
    for (int i = 0; i < 16; i++) {
        int idx = tid + i * 256;
        int r = idx >> 6, t = idx & 63;
        kvs[r][t] = kvl[(size_t)r * DDIM + h * HD + t];
    }
    __syncthreads();
    const int eloc = tid & 127, rbase = tid >> 7;   // rbase 0/1
    float acc[32];
    #pragma unroll
    for (int i = 0; i < 32; i++) acc[i] = 0.f;
    for (int t2 = 0; t2 < 64; t2 += 2) {
        woS[rbase][eloc] = wo[(size_t)(h * HD + t2 + rbase) * DDIM + ebase + eloc];
        __syncthreads();
        #pragma unroll
        for (int tt = 0; tt < 2; tt++) {
            float w = woS[tt][eloc];
            #pragma unroll
            for (int i = 0; i < 32; i++)
                acc[i] += kvs[rbase + 2 * i][t2 + tt] * w;
        }
        __syncthreads();
    }
    #pragma unroll
    for (int i = 0; i < 32; i++)
        P[(size_t)(h * HD + rbase + 2 * i) * DDIM + ebase + eloc] = acc[i];
}

// ---------------------------------------------------------------------------
// k_tw1: W1T[n][k] = fp16(w1[k][n])   (transpose, fp32 -> fp16)
// ---------------------------------------------------------------------------
__global__ void k_tw1(const float* __restrict__ W, __half* __restrict__ WT) {
    __shared__ float t[32][33];
    int bx = blockIdx.x * 32, by = blockIdx.y * 32;
    int tx = threadIdx.x & 31, ty = threadIdx.x >> 5;  // 8 rows
    #pragma unroll
    for (int i = 0; i < 4; i++)
        t[ty + 8*i][tx] = W[(size_t)(by + ty + 8*i)*DDIM + bx + tx];
    __syncthreads();
    #pragma unroll
    for (int i = 0; i < 4; i++)
        WT[(size_t)(bx + ty + 8*i)*DDIM + by + tx] = __float2half_rn(t[tx][ty + 8*i]);
}

// ---------------------------------------------------------------------------
// k_final: out[b,e] = b2[e] + (Gsum[b]/S) @ w2[:,e] + (Asum[b]/S) @ P[:,e]
// ---------------------------------------------------------------------------
__global__ void k_final(const float* __restrict__ w2, const float* __restrict__ b2,
                        const float* __restrict__ Gsum, const float* __restrict__ Asum,
                        const float* __restrict__ P, float* __restrict__ out) {
    int b = blockIdx.y;
    int e = blockIdx.x * 256 + threadIdx.x;
    __shared__ float gs[DDIM], as[DDIM];
    const float invS = 1.f / (float)SEQ;
    for (int i = threadIdx.x; i < DDIM; i += 256) {
        gs[i] = Gsum[b*DDIM + i] * invS;
        as[i] = Asum[b*DDIM + i] * invS;
    }
    __syncthreads();
    float a0 = 0.f, a1 = 0.f, a2 = 0.f, a3 = 0.f;
    for (int k = 0; k < DDIM; k += 4) {
        a0 = fmaf(gs[k  ], w2[(size_t)(k  )*DDIM + e], fmaf(as[k  ], P[(size_t)(k  )*DDIM + e], a0));
        a1 = fmaf(gs[k+1], w2[(size_t)(k+1)*DDIM + e], fmaf(as[k+1], P[(size_t)(k+1)*DDIM + e], a1));
        a2 = fmaf(gs[k+2], w2[(size_t)(k+2)*DDIM + e], fmaf(as[k+2], P[(size_t)(k+2)*DDIM + e], a2));
        a3 = fmaf(gs[k+3], w2[(size_t)(k+3)*DDIM + e], fmaf(as[k+3], P[(size_t)(k+3)*DDIM + e], a3));
    }
    out[b*DDIM + e] = b2[e] + ((a0 + a1) + (a2 + a3));
}

// ---------------------------------------------------------------------------
// Host launcher
// ---------------------------------------------------------------------------
extern "C" void kernel_launch(void* const* d_in, const int* in_sizes, int n_in,
                              void* d_out, int out_size) {
    const float* x   = (const float*)d_in[0];
    const float* wq  = (const float*)d_in[1];
    const float* kvl = (const float*)d_in[2];
    const float* wo  = (const float*)d_in[3];
    const float* w1  = (const float*)d_in[4];
    const float* b1  = (const float*)d_in[5];
    const float* w2  = (const float*)d_in[6];
    const float* b2  = (const float*)d_in[7];
    float* out = (float*)d_out;

    float *pP, *pG, *pA;
    __half *pW1T, *pB1, *pB2, *pAttnH;
    cudaGetSymbolAddress((void**)&pP,     g_P);
    cudaGetSymbolAddress((void**)&pG,     g_Gsum);
    cudaGetSymbolAddress((void**)&pA,     g_Asum);
    cudaGetSymbolAddress((void**)&pW1T,   g_W1T);
    cudaGetSymbolAddress((void**)&pB1,    g_B1);
    cudaGetSymbolAddress((void**)&pB2,    g_B2);
    cudaGetSymbolAddress((void**)&pAttnH, g_attnH);

    cudaFuncSetAttribute(wm_gemm<0,0>, cudaFuncAttributeMaxDynamicSharedMemorySize, SMEM_M1);
    cudaFuncSetAttribute(wm_gemm<1,0>, cudaFuncAttributeMaxDynamicSharedMemorySize, SMEM_M1);
    cudaFuncSetAttribute(wm_gemm<2,1>, cudaFuncAttributeMaxDynamicSharedMemorySize, SMEM_M2);

    // 1. zero accumulators
    k_zero<<<(BATCH*DDIM + 255)/256, 256>>>(pG, pA);
    // 2. folded weights: B1 (fp16 transposed) and P (fp32)
    k_wl<<<dim3(8, NHEAD), 256>>>(wq, kvl, pB1);
    k_p <<<dim3(8, NHEAD), 256>>>(kvl, wo, pP);
    // 3. B2 = (P @ w1)^T fp16, on tensor cores
    k_tw1<<<dim3(32, 32), 256>>>(w1, pW1T);
    wm_gemm<0,0><<<dim3(8, 8), 256, SMEM_M1>>>(pP, nullptr, pW1T, nullptr, pB2, nullptr);
    // 4. attn = softmax(x @ Wl); Asum accumulated  [mma.sync fp16 x1]
    wm_gemm<1,0><<<dim3(8, NTOK/128), 256, SMEM_M1>>>(x, nullptr, pB1, nullptr, pAttnH, pA);
    // 5. Gsum += colsum(gelu(attn @ Q1 + b1))       [mma.sync fp16 x1, A=fp16]
    wm_gemm<2,1><<<dim3(8, NTOK/128), 256, SMEM_M2>>>(nullptr, pAttnH, pB2, b1, nullptr, pG);
    // 6. final tiny GEMMs + bias + residual mean
    k_final<<<dim3(4, BATCH), 256>>>(w2, b2, pG, pA, pP, out);
}